// round 9
// baseline (speedup 1.0000x reference)
#include <cuda_runtime.h>
#include <math.h>
#include <stdint.h>

constexpr int B_  = 4;
constexpr int L_  = 512;
constexpr int D_  = 768;
constexpr int H_  = 12;
constexpr int M_  = B_ * L_;
constexpr float SCALE_    = 0.08838834764831845f;
constexpr float INVSQRT2_ = 0.70710678118654752f;
constexpr float CAP_      = 5.0f;

// Scratch
__device__ float g_q   [M_ * D_];
__device__ float g_k   [M_ * D_];
__device__ float g_v   [M_ * D_];
__device__ float g_eb  [B_ * L_ * L_];                // eb with mask folded in
__device__ float g_attn[(size_t)B_ * H_ * L_ * L_];
__device__ float g_cat [M_ * 2 * D_];
__device__ float g_W2  [D_ * D_];
__device__ float g_W3  [D_ * D_];
__device__ float g_b2  [D_];
__device__ float g_b3  [D_];

// ----------------------------------------------------------------------------
// helpers
// ----------------------------------------------------------------------------
__device__ __forceinline__ unsigned f2tf(float x) {
    unsigned u;
    asm("cvt.rna.tf32.f32 %0, %1;" : "=r"(u) : "f"(x));
    return u;
}
__device__ __forceinline__ unsigned cvt_u(unsigned x) {
    return f2tf(__uint_as_float(x));
}
__device__ __forceinline__ void mma8(float* c, const unsigned* a, const unsigned* b) {
    asm volatile(
        "mma.sync.aligned.m16n8k8.row.col.f32.tf32.tf32.f32 "
        "{%0,%1,%2,%3}, {%4,%5,%6,%7}, {%8,%9}, {%0,%1,%2,%3};"
        : "+f"(c[0]), "+f"(c[1]), "+f"(c[2]), "+f"(c[3])
        : "r"(a[0]), "r"(a[1]), "r"(a[2]), "r"(a[3]), "r"(b[0]), "r"(b[1]));
}
__device__ __forceinline__ unsigned smem_u32(const void* p) {
    return (unsigned)__cvta_generic_to_shared(p);
}
__device__ __forceinline__ void ldsm4(unsigned* r, unsigned a) {
    asm volatile("ldmatrix.sync.aligned.m8n8.x4.shared.b16 {%0,%1,%2,%3}, [%4];"
        : "=r"(r[0]), "=r"(r[1]), "=r"(r[2]), "=r"(r[3]) : "r"(a));
}
__device__ __forceinline__ void cp16(unsigned dst, const void* src) {
    asm volatile("cp.async.cg.shared.global [%0], [%1], 16;" :: "r"(dst), "l"(src));
}
__device__ __forceinline__ void cp_commit() {
    asm volatile("cp.async.commit_group;");
}
template<int N>
__device__ __forceinline__ void cp_wait() {
    asm volatile("cp.async.wait_group %0;" :: "n"(N));
}

struct GArg  { const float* A; const float* Bm; const float* B2; const float* bias; float* C; };
struct GArgs { GArg g[3]; int K; int K1; int lda; };

// ----------------------------------------------------------------------------
// NN tf32 GEMM: BM=128 BN=128 BK=16, 256 threads (8 warps, warp tile 32x64),
// cp.async 3-stage, dynamic smem (56832 B), in-loop cvt. Requires (K/16)%3==0.
// ----------------------------------------------------------------------------
constexpr int GNN_SMEM = (3 * 128 * 20 + 3 * 16 * 136) * 4;   // 56832

template<bool BIAS>
__global__ void __launch_bounds__(256, 2) gemm_nn(GArgs args)
{
    extern __shared__ unsigned dyn[];
    unsigned* Asb[3] = { dyn, dyn + 2560, dyn + 5120 };
    unsigned* Bsb[3] = { dyn + 7680, dyn + 7680 + 2176, dyn + 7680 + 4352 };

    const GArg ga = args.g[blockIdx.z];
    const int K  = args.K;
    const int K1 = args.K1;
    const int T  = K >> 4;

    const int tid  = threadIdx.x;
    const int lane = tid & 31;
    const int wid  = tid >> 5;
    const int grp  = lane >> 2;
    const int tig  = lane & 3;
    const int wm0  = (wid >> 1) * 32;
    const int wn0  = (wid & 1) * 64;
    const int m0   = blockIdx.y * 128;
    const int n0   = blockIdx.x * 128;

    float acc[2][8][4];
#pragma unroll
    for (int i = 0; i < 2; i++)
#pragma unroll
        for (int j = 0; j < 8; j++)
#pragma unroll
            for (int q = 0; q < 4; q++) acc[i][j][q] = 0.f;

    const int a_r = tid >> 1, a_c = (tid & 1) * 8;
    const int b_r = tid >> 4, b_c = (tid & 15) * 8;
    const float* Agbase = ga.A + (size_t)(m0 + a_r) * K + a_c;
    const unsigned a_off = (unsigned)((a_r * 20 + a_c) * 4);
    const unsigned b_off = (unsigned)((b_r * 136 + b_c) * 4);

    const int lrow = wm0 + (lane & 7) + 8 * ((lane >> 3) & 1);
    const int lcol = 4 * (lane >> 4);
    unsigned abf[3];
#pragma unroll
    for (int i = 0; i < 3; i++)
        abf[i] = smem_u32(Asb[i]) + (unsigned)((lrow * 20 + lcol) * 4);
    unsigned asd[3], bsd[3];
#pragma unroll
    for (int i = 0; i < 3; i++) { asd[i] = smem_u32(Asb[i]); bsd[i] = smem_u32(Bsb[i]); }

    auto cp_tile = [&](int it, int buf) {
        const int kk = it * 16;
        const float* as = Agbase + kk;
        cp16(asd[buf] + a_off, as);
        cp16(asd[buf] + a_off + 16, as + 4);
        const int krow = kk + b_r;
        const float* bsrc = (krow < K1 ? ga.Bm + (size_t)krow * 768
                                       : ga.B2 + (size_t)(krow - K1) * 768) + n0 + b_c;
        cp16(bsd[buf] + b_off, bsrc);
        cp16(bsd[buf] + b_off + 16, bsrc + 4);
    };

    auto mma_tile = [&](int buf) {
        const unsigned abase = abf[buf];
        const unsigned* Bp = Bsb[buf];
#pragma unroll
        for (int kc = 0; kc < 16; kc += 8) {
            unsigned af[2][4];
            ldsm4(af[0], abase + (unsigned)(kc * 4));
            ldsm4(af[1], abase + (unsigned)((16 * 20 + kc) * 4));
#pragma unroll
            for (int i = 0; i < 2; i++)
#pragma unroll
                for (int q = 0; q < 4; q++) af[i][q] = cvt_u(af[i][q]);
            unsigned bf[8][2];
#pragma unroll
            for (int j = 0; j < 8; j++) {
                bf[j][0] = cvt_u(Bp[(kc + tig) * 136 + wn0 + j * 8 + grp]);
                bf[j][1] = cvt_u(Bp[(kc + tig + 4) * 136 + wn0 + j * 8 + grp]);
            }
#pragma unroll
            for (int i = 0; i < 2; i++)
#pragma unroll
                for (int j = 0; j < 8; j++) mma8(acc[i][j], af[i], bf[j]);
        }
    };

    cp_tile(0, 0); cp_commit();
    cp_tile(1, 1); cp_commit();

    for (int it = 0; it < T; it += 3) {
        cp_wait<1>(); __syncthreads();
        if (it + 2 < T) cp_tile(it + 2, 2);
        cp_commit();
        mma_tile(0);

        cp_wait<1>(); __syncthreads();
        if (it + 3 < T) cp_tile(it + 3, 0);
        cp_commit();
        mma_tile(1);

        cp_wait<1>(); __syncthreads();
        if (it + 4 < T) cp_tile(it + 4, 1);
        cp_commit();
        mma_tile(2);
    }

#pragma unroll
    for (int i = 0; i < 2; i++) {
        int r0 = m0 + wm0 + i * 16 + grp;
#pragma unroll
        for (int j = 0; j < 8; j++) {
            int c = n0 + wn0 + j * 8 + 2 * tig;
            float b0 = 0.f, b1 = 0.f;
            if (BIAS) { b0 = ga.bias[c]; b1 = ga.bias[c + 1]; }
            *(float2*)&ga.C[(size_t)r0 * 768 + c] =
                make_float2(acc[i][j][0] + b0, acc[i][j][1] + b1);
            *(float2*)&ga.C[(size_t)(r0 + 8) * 768 + c] =
                make_float2(acc[i][j][2] + b0, acc[i][j][3] + b1);
        }
    }
}

// ----------------------------------------------------------------------------
// NN tf32 GEMM: BM=64 BN=128, 128 thr, cp.async 3-stage (unchanged from R8).
// ----------------------------------------------------------------------------
template<bool BIAS, bool ACC>
__global__ void __launch_bounds__(128, 3) gemm_nn64(GArgs args)
{
    const GArg ga = args.g[blockIdx.z];
    const int K   = args.K;
    const int K1  = args.K1;
    const int lda = args.lda;
    const int T   = K >> 4;

    __shared__ alignas(16) unsigned As[3][64 * 20];
    __shared__ alignas(16) unsigned Bs[3][16 * 136];

    const int tid  = threadIdx.x;
    const int lane = tid & 31;
    const int wid  = tid >> 5;
    const int grp  = lane >> 2;
    const int tig  = lane & 3;
    const int wm0  = (wid >> 1) * 32;
    const int wn0  = (wid & 1) * 64;
    const int m0   = blockIdx.y * 64;
    const int n0   = blockIdx.x * 128;

    float acc[2][8][4];
#pragma unroll
    for (int i = 0; i < 2; i++)
#pragma unroll
        for (int j = 0; j < 8; j++)
#pragma unroll
            for (int q = 0; q < 4; q++) acc[i][j][q] = 0.f;

    const int a_r = tid >> 1;
    const int a_c = (tid & 1) * 8;
    const float* Agbase = ga.A + (size_t)(m0 + a_r) * lda + a_c;
    const unsigned a_off = (unsigned)((a_r * 20 + a_c) * 4);
    const int b_r = tid >> 3;
    const int b_c = (tid & 7) * 16;
    const unsigned b_off = (unsigned)((b_r * 136 + b_c) * 4);

    const int lrow = wm0 + (lane & 7) + 8 * ((lane >> 3) & 1);
    const int lcol = 4 * (lane >> 4);
    const unsigned ab0 = smem_u32(As[0]) + (unsigned)((lrow * 20 + lcol) * 4);
    const unsigned ab1 = smem_u32(As[1]) + (unsigned)((lrow * 20 + lcol) * 4);
    const unsigned ab2 = smem_u32(As[2]) + (unsigned)((lrow * 20 + lcol) * 4);

    auto cp_tile = [&](int it, unsigned adst, unsigned bdst) {
        const int kk = it * 16;
        const float* as = Agbase + kk;
#pragma unroll
        for (int c = 0; c < 2; c++) cp16(adst + a_off + c * 16, as + c * 4);
        const int krow = kk + b_r;
        const float* bsrc = (krow < K1 ? ga.Bm + (size_t)krow * 768
                                       : ga.B2 + (size_t)(krow - K1) * 768) + n0 + b_c;
#pragma unroll
        for (int c = 0; c < 4; c++) cp16(bdst + b_off + c * 16, bsrc + c * 4);
    };

    auto mma_tile = [&](unsigned abase, const unsigned* Bsb) {
#pragma unroll
        for (int kc = 0; kc < 16; kc += 8) {
            unsigned af[2][4];
#pragma unroll
            for (int i = 0; i < 2; i++) {
                ldsm4(af[i], abase + (unsigned)((i * 16 * 20 + kc) * 4));
#pragma unroll
                for (int q = 0; q < 4; q++) af[i][q] = cvt_u(af[i][q]);
            }
            unsigned bf[8][2];
#pragma unroll
            for (int j = 0; j < 8; j++) {
                bf[j][0] = cvt_u(Bsb[(kc + tig) * 136 + wn0 + j * 8 + grp]);
                bf[j][1] = cvt_u(Bsb[(kc + tig + 4) * 136 + wn0 + j * 8 + grp]);
            }
#pragma unroll
            for (int i = 0; i < 2; i++)
#pragma unroll
                for (int j = 0; j < 8; j++) mma8(acc[i][j], af[i], bf[j]);
        }
    };

    const unsigned asd0 = smem_u32(As[0]), asd1 = smem_u32(As[1]), asd2 = smem_u32(As[2]);
    const unsigned bsd0 = smem_u32(Bs[0]), bsd1 = smem_u32(Bs[1]), bsd2 = smem_u32(Bs[2]);

    cp_tile(0, asd0, bsd0); cp_commit();
    cp_tile(1, asd1, bsd1); cp_commit();

    for (int it = 0; it < T; it += 3) {
        cp_wait<1>(); __syncthreads();
        if (it + 2 < T) cp_tile(it + 2, asd2, bsd2);
        cp_commit();
        mma_tile(ab0, Bs[0]);

        cp_wait<1>(); __syncthreads();
        if (it + 3 < T) cp_tile(it + 3, asd0, bsd0);
        cp_commit();
        mma_tile(ab1, Bs[1]);

        cp_wait<1>(); __syncthreads();
        if (it + 4 < T) cp_tile(it + 4, asd1, bsd1);
        cp_commit();
        mma_tile(ab2, Bs[2]);
    }

#pragma unroll
    for (int i = 0; i < 2; i++) {
        int r0 = m0 + wm0 + i * 16 + grp;
#pragma unroll
        for (int j = 0; j < 8; j++) {
            int c = n0 + wn0 + j * 8 + 2 * tig;
            float b0 = 0.f, b1 = 0.f;
            if (BIAS) { b0 = ga.bias[c]; b1 = ga.bias[c + 1]; }
            float2 o0 = make_float2(acc[i][j][0] + b0, acc[i][j][1] + b1);
            float2 o1 = make_float2(acc[i][j][2] + b0, acc[i][j][3] + b1);
            float2* p0 = (float2*)&ga.C[(size_t)r0 * 768 + c];
            float2* p1 = (float2*)&ga.C[(size_t)(r0 + 8) * 768 + c];
            if (ACC) {
                float2 e0 = *p0, e1 = *p1;
                o0.x += e0.x; o0.y += e0.y; o1.x += e1.x; o1.y += e1.y;
            }
            *p0 = o0; *p1 = o1;
        }
    }
}

// ----------------------------------------------------------------------------
// Fused attention, 32 q-rows/CTA, 64-row K/V chunks, 256 threads.
// smem 109568 B -> 2 CTAs/SM. grid (16, 48).
// ----------------------------------------------------------------------------
constexpr int SC_STRIDE = 516;
constexpr int SC_BYTES  = 32 * SC_STRIDE * 4;        // 66048
constexpr int QS_BYTES  = 32 * 68 * 4;               // 8704
constexpr int KV_BYTES  = 64 * 68 * 4;               // 17408
constexpr int ATTN_SMEM = SC_BYTES + QS_BYTES + 2 * KV_BYTES;  // 109568

__global__ void __launch_bounds__(256, 2) attn_fused()
{
    extern __shared__ char dsm[];
    float*    Sc  = (float*)dsm;                          // 32 x 516
    unsigned* Qs  = (unsigned*)(dsm + SC_BYTES);          // 32 x 68
    unsigned* Kv0 = (unsigned*)(dsm + SC_BYTES + QS_BYTES);
    unsigned* Kv1 = Kv0 + 64 * 68;

    const int bh = blockIdx.y;
    const int b  = bh / H_;
    const int h  = bh % H_;
    const int n0 = blockIdx.x * 32;

    const int tid  = threadIdx.x;
    const int lane = tid & 31;
    const int w    = tid >> 5;          // 0..7
    const int grp  = lane >> 2;
    const int tig  = lane & 3;

    // ---- Phase 1: Q (32x64) tf32 ----
    {
        int row = tid >> 3, col = (tid & 7) * 8;
        const float* src = g_q + (size_t)(b * 512 + n0 + row) * 768 + h * 64 + col;
        float4 q0 = *(const float4*)src;
        float4 q1 = *(const float4*)(src + 4);
        *(uint4*)&Qs[row * 68 + col]     = make_uint4(f2tf(q0.x), f2tf(q0.y), f2tf(q0.z), f2tf(q0.w));
        *(uint4*)&Qs[row * 68 + col + 4] = make_uint4(f2tf(q1.x), f2tf(q1.y), f2tf(q1.z), f2tf(q1.w));
    }

    // chunk staging: 64 rows x 64 cols, 256 threads x 16 floats
    const int srow = tid >> 2;
    const int scol = (tid & 3) * 16;
    float4 st[4];
    auto ldg_chunk = [&](const float* basep, int mc) {
        const float* s = basep + (size_t)(b * 512 + mc + srow) * 768 + h * 64 + scol;
        st[0] = *(const float4*)(s);
        st[1] = *(const float4*)(s + 4);
        st[2] = *(const float4*)(s + 8);
        st[3] = *(const float4*)(s + 12);
    };
    auto sts_chunk = [&](unsigned* buf) {
#pragma unroll
        for (int c = 0; c < 4; c++)
            *(uint4*)&buf[srow * 68 + scol + c * 4] =
                make_uint4(f2tf(st[c].x), f2tf(st[c].y), f2tf(st[c].z), f2tf(st[c].w));
    };

    ldg_chunk(g_k, 0);
    sts_chunk(Kv0);
    __syncthreads();

    // ---- Phase 2: scores over 8 m-chunks of 64 ----
    const int qb = (w >> 2) * 16;      // 0 or 16
    const int mb = (w & 3) * 16;       // 0..48
    const unsigned aq0 = smem_u32(Qs) +
        (unsigned)(((qb + (lane & 7) + 8 * ((lane >> 3) & 1)) * 68 + 4 * (lane >> 4)) * 4);
    const unsigned koff =
        (unsigned)(((mb + (lane & 7) + 8 * (lane >> 4)) * 68 + 4 * ((lane >> 3) & 1)) * 4);
    const unsigned kvb[2] = { smem_u32(Kv0), smem_u32(Kv1) };

    for (int c = 0; c < 8; c++) {
        if (c < 7) ldg_chunk(g_k, (c + 1) * 64);
        float acc[2][4];
#pragma unroll
        for (int j = 0; j < 2; j++)
#pragma unroll
            for (int q = 0; q < 4; q++) acc[j][q] = 0.f;

        const unsigned kb = kvb[c & 1] + koff;
#pragma unroll
        for (int kc = 0; kc < 64; kc += 8) {
            unsigned af[4];
            ldsm4(af, aq0 + (unsigned)(kc * 4));
            unsigned t[4];
            ldsm4(t, kb + (unsigned)(kc * 4));
            unsigned bf0[2] = { t[0], t[1] };
            unsigned bf1[2] = { t[2], t[3] };
            mma8(acc[0], af, bf0);
            mma8(acc[1], af, bf1);
        }

        const int mc = c * 64;
#pragma unroll
        for (int p = 0; p < 2; p++) {
            int row = qb + grp + p * 8;
#pragma unroll
            for (int mt = 0; mt < 2; mt++) {
                int col = mc + mb + mt * 8 + 2 * tig;
                size_t em = (size_t)(b * 512 + n0 + row) * 512 + col;
                float2 e2 = *(const float2*)&g_eb[em];   // mask folded in
                *(float2*)&Sc[row * SC_STRIDE + col] =
                    make_float2(acc[mt][2 * p]     * SCALE_ + e2.x,
                                acc[mt][2 * p + 1] * SCALE_ + e2.y);
            }
        }
        if (c < 7) sts_chunk((c & 1) ? Kv0 : Kv1);
        __syncthreads();
    }

    // prefetch V chunk 0 (overlaps softmax)
    ldg_chunk(g_v, 0);

    // ---- Phase 3: softmax in smem; write attn; keep tf32 copy in Sc ----
#pragma unroll
    for (int r = 0; r < 4; r++) {
        int row = w * 4 + r;
        float4 v[4];
#pragma unroll
        for (int j = 0; j < 4; j++)
            v[j] = *(float4*)&Sc[row * SC_STRIDE + lane * 4 + j * 128];
        float mx = -1e30f;
#pragma unroll
        for (int j = 0; j < 4; j++)
            mx = fmaxf(mx, fmaxf(fmaxf(v[j].x, v[j].y), fmaxf(v[j].z, v[j].w)));
#pragma unroll
        for (int o = 16; o > 0; o >>= 1)
            mx = fmaxf(mx, __shfl_xor_sync(0xffffffffu, mx, o));
        float sum = 0.f;
#pragma unroll
        for (int j = 0; j < 4; j++) {
            v[j].x = __expf(v[j].x - mx); v[j].y = __expf(v[j].y - mx);
            v[j].z = __expf(v[j].z - mx); v[j].w = __expf(v[j].w - mx);
            sum += v[j].x + v[j].y + v[j].z + v[j].w;
        }
#pragma unroll
        for (int o = 16; o > 0; o >>= 1)
            sum += __shfl_xor_sync(0xffffffffu, sum, o);
        float inv = 1.0f / sum;
        float4* gout = (float4*)&g_attn[((size_t)bh * 512 + n0 + row) * 512];
#pragma unroll
        for (int j = 0; j < 4; j++) {
            float4 nv = make_float4(v[j].x * inv, v[j].y * inv, v[j].z * inv, v[j].w * inv);
            gout[lane + j * 32] = nv;
            *(uint4*)&Sc[row * SC_STRIDE + lane * 4 + j * 128] =
                make_uint4(f2tf(nv.x), f2tf(nv.y), f2tf(nv.z), f2tf(nv.w));
        }
    }
    sts_chunk(Kv0);
    __syncthreads();

    // ---- Phase 4: ctx = attn @ v ----
    const int db = (w & 3) * 16;       // 0..48
    float acc2[2][4];
#pragma unroll
    for (int i = 0; i < 2; i++)
#pragma unroll
        for (int q = 0; q < 4; q++) acc2[i][q] = 0.f;

    const unsigned as0 = smem_u32(Sc) +
        (unsigned)(((qb + (lane & 7) + 8 * ((lane >> 3) & 1)) * SC_STRIDE + 4 * (lane >> 4)) * 4);

    for (int c = 0; c < 8; c++) {
        if (c < 7) ldg_chunk(g_v, (c + 1) * 64);
        const unsigned* kvu = (c & 1) ? Kv1 : Kv0;
#pragma unroll
        for (int ml = 0; ml < 64; ml += 8) {
            unsigned af[4];
            ldsm4(af, as0 + (unsigned)((c * 64 + ml) * 4));
            unsigned bf0[2], bf1[2];
            bf0[0] = kvu[(ml + tig) * 68 + db + grp];
            bf0[1] = kvu[(ml + tig + 4) * 68 + db + grp];
            bf1[0] = kvu[(ml + tig) * 68 + db + 8 + grp];
            bf1[1] = kvu[(ml + tig + 4) * 68 + db + 8 + grp];
            mma8(acc2[0], af, bf0);
            mma8(acc2[1], af, bf1);
        }
        if (c < 7) sts_chunk((c & 1) ? Kv0 : Kv1);
        __syncthreads();
    }

#pragma unroll
    for (int p = 0; p < 2; p++) {
        int row = qb + grp + p * 8;
#pragma unroll
        for (int nt = 0; nt < 2; nt++) {
            int col = h * 64 + db + nt * 8 + 2 * tig;
            *(float2*)&g_cat[(size_t)(b * 512 + n0 + row) * 1536 + col] =
                make_float2(acc2[nt][2 * p], acc2[nt][2 * p + 1]);
        }
    }
}

// ----------------------------------------------------------------------------
// Weight folds (side stream)
// ----------------------------------------------------------------------------
__global__ void __launch_bounds__(256) build_w2_tile(
    const float* __restrict__ Wke, const float* __restrict__ Weo)
{
    __shared__ float Ws[64 * 64];
    const int tid = threadIdx.x;
    const int h   = blockIdx.y;
    const int j0  = blockIdx.x * 128;

#pragma unroll
    for (int i = 0; i < 16; i++)
        Ws[tid + i * 256] = Wke[tid + i * 256];
    __syncthreads();

    const int jl = tid & 127;
    const int c0 = (tid >> 7) * 32;
    float acc[32];
#pragma unroll
    for (int c = 0; c < 32; c++) acc[c] = 0.f;

    for (int e = 0; e < 64; e++) {
        float w = Weo[(size_t)(h * 64 + e) * 768 + j0 + jl];
#pragma unroll
        for (int c = 0; c < 32; c++)
            acc[c] += Ws[(c0 + c) * 64 + e] * w;
    }
#pragma unroll
    for (int c = 0; c < 32; c++)
        g_W2[(size_t)(h * 64 + c0 + c) * 768 + j0 + jl] = acc[c];
}

__global__ void __launch_bounds__(256) build_b2_par(
    const float* __restrict__ bke, const float* __restrict__ Weo,
    const float* __restrict__ beo)
{
    __shared__ float red[8][32];
    const int tid = threadIdx.x;
    const int jl  = tid & 31;
    const int rw  = tid >> 5;
    const int j   = blockIdx.x * 32 + jl;

    float acc = 0.f;
    for (int r = rw; r < 768; r += 8)
        acc += bke[r & 63] * Weo[(size_t)r * 768 + j];
    red[rw][jl] = acc;
    __syncthreads();
    if (rw == 0) {
        float s = beo[j];
#pragma unroll
        for (int i = 0; i < 8; i++) s += red[i][jl];
        g_b2[j] = s;
    }
}

__global__ void __launch_bounds__(256) build_b3_par(
    const float* __restrict__ Wo2, const float* __restrict__ bo)
{
    __shared__ float red[8][32];
    const int tid = threadIdx.x;
    const int jl  = tid & 31;
    const int rw  = tid >> 5;
    const int j   = blockIdx.x * 32 + jl;

    float acc = 0.f;
    for (int r = rw; r < 768; r += 8)
        acc += g_b2[r] * Wo2[(size_t)r * 768 + j];
    red[rw][jl] = acc;
    __syncthreads();
    if (rw == 0) {
        float s = bo[j];
#pragma unroll
        for (int i = 0; i < 8; i++) s += red[i][jl];
        g_b3[j] = s;
    }
}

// ----------------------------------------------------------------------------
// Edge bias (softcap) with mask folded: ebm = mask ? -1e9 : cap*tanh(...)
// ----------------------------------------------------------------------------
__global__ void __launch_bounds__(256) eb_kernel(
    const float* __restrict__ edge, const float* __restrict__ We,
    const float* __restrict__ be, const unsigned char* __restrict__ mask)
{
    int idx  = blockIdx.x * 16 + (threadIdx.x >> 4);
    int l16  = threadIdx.x & 15;
    const float4 e4 = *(const float4*)(edge + (size_t)idx * 64 + l16 * 4);
    const float4 w4 = *(const float4*)(We + l16 * 4);
    float acc = e4.x * w4.x + e4.y * w4.y + e4.z * w4.z + e4.w * w4.w;
#pragma unroll
    for (int o = 8; o > 0; o >>= 1)
        acc += __shfl_xor_sync(0xffffffffu, acc, o);
    if (l16 == 0) {
        float x = (acc + be[0]) * INVSQRT2_;
        float r = CAP_ * tanhf(x * (1.0f / CAP_));
        g_eb[idx] = mask[idx] ? -1e9f : r;
    }
}

// ----------------------------------------------------------------------------
// ae -> g_cat[:, 768:1536]
// ----------------------------------------------------------------------------
__global__ void __launch_bounds__(256) ae_kernel(const float* __restrict__ edge)
{
    const int bn = blockIdx.x;
    const int b  = bn >> 9;
    const int n  = bn & 511;

    __shared__ float Es[64 * 64];
    __shared__ float Asm[12 * 64];

    const int tid = threadIdx.x;
    const int d   = tid & 63;
    const int h0  = tid >> 6;

    float acc0 = 0.f, acc1 = 0.f, acc2 = 0.f;
    const float* ebase = edge + (size_t)bn * 512 * 64;

    for (int mc = 0; mc < 512; mc += 64) {
        const float4* eg = (const float4*)(ebase + (size_t)mc * 64);
        float4* es4 = (float4*)Es;
#pragma unroll
        for (int i = 0; i < 4; i++)
            es4[tid + i * 256] = eg[tid + i * 256];
#pragma unroll
        for (int i = 0; i < 3; i++) {
            int lin = tid + i * 256;
            int hh = lin >> 6, mm = lin & 63;
            Asm[lin] = g_attn[(((size_t)(b * H_ + hh)) * 512 + n) * 512 + mc + mm];
        }
        __syncthreads();
#pragma unroll 4
        for (int m = 0; m < 64; m += 4) {
            float4 a0 = *(const float4*)&Asm[(h0    ) * 64 + m];
            float4 a1 = *(const float4*)&Asm[(h0 + 4) * 64 + m];
            float4 a2 = *(const float4*)&Asm[(h0 + 8) * 64 + m];
            float e0 = Es[(m + 0) * 64 + d];
            float e1 = Es[(m + 1) * 64 + d];
            float e2 = Es[(m + 2) * 64 + d];
            float e3 = Es[(m + 3) * 64 + d];
            acc0 += a0.x * e0 + a0.y * e1 + a0.z * e2 + a0.w * e3;
            acc1 += a1.x * e0 + a1.y * e1 + a1.z * e2 + a1.w * e3;
            acc2 += a2.x * e0 + a2.y * e1 + a2.z * e2 + a2.w * e3;
        }
        __syncthreads();
    }

    float* ar = g_cat + (size_t)bn * 1536 + 768;
    ar[(h0    ) * 64 + d] = acc0;
    ar[(h0 + 4) * 64 + d] = acc1;
    ar[(h0 + 8) * 64 + d] = acc2;
}

// ----------------------------------------------------------------------------
// Launch. Critical: QKV(idx 3) -> attn_fused -> final1 -> final2.
// Side s1: eb(+mask), folds, W3, ae.
// ----------------------------------------------------------------------------
extern "C" void kernel_launch(void* const* d_in, const int* in_sizes, int n_in,
                              void* d_out, int out_size)
{
    const float* Q    = (const float*)d_in[0];
    const float* Kin  = (const float*)d_in[1];
    const float* V    = (const float*)d_in[2];
    const unsigned char* mask = (const unsigned char*)d_in[3];
    const float* edge = (const float*)d_in[4];
    const float* Wq   = (const float*)d_in[5];
    const float* bq   = (const float*)d_in[6];
    const float* Wk   = (const float*)d_in[7];
    const float* bk   = (const float*)d_in[8];
    const float* Wv   = (const float*)d_in[9];
    const float* bv   = (const float*)d_in[10];
    const float* Wke  = (const float*)d_in[11];
    const float* bke  = (const float*)d_in[12];
    const float* We   = (const float*)d_in[13];
    const float* be   = (const float*)d_in[14];
    const float* Weo  = (const float*)d_in[15];
    const float* beo  = (const float*)d_in[16];
    const float* Wo   = (const float*)d_in[17];
    const float* bo   = (const float*)d_in[18];
    float* out = (float*)d_out;

    void *pq, *pk, *pv, *pcat, *pW2, *pW3, *pb3;
    cudaGetSymbolAddress(&pq,   g_q);
    cudaGetSymbolAddress(&pk,   g_k);
    cudaGetSymbolAddress(&pv,   g_v);
    cudaGetSymbolAddress(&pcat, g_cat);
    cudaGetSymbolAddress(&pW2,  g_W2);
    cudaGetSymbolAddress(&pW3,  g_W3);
    cudaGetSymbolAddress(&pb3,  g_b3);

    static cudaStream_t s1 = nullptr;
    static cudaEvent_t evA = nullptr, evB = nullptr, evC = nullptr, evD = nullptr, evE = nullptr;
    if (!s1) {
        cudaStreamCreateWithFlags(&s1, cudaStreamNonBlocking);
        cudaEventCreateWithFlags(&evA, cudaEventDisableTiming);
        cudaEventCreateWithFlags(&evB, cudaEventDisableTiming);
        cudaEventCreateWithFlags(&evC, cudaEventDisableTiming);
        cudaEventCreateWithFlags(&evD, cudaEventDisableTiming);
        cudaEventCreateWithFlags(&evE, cudaEventDisableTiming);
        cudaFuncSetAttribute(attn_fused, cudaFuncAttributeMaxDynamicSharedMemorySize, ATTN_SMEM);
        cudaFuncSetAttribute(gemm_nn<true>,  cudaFuncAttributeMaxDynamicSharedMemorySize, GNN_SMEM);
        cudaFuncSetAttribute(gemm_nn<false>, cudaFuncAttributeMaxDynamicSharedMemorySize, GNN_SMEM);
    }

    cudaEventRecord(evA, 0);
    cudaStreamWaitEvent(s1, evA, 0);

    eb_kernel<<<(B_ * L_ * L_) / 16, 256, 0, s1>>>(edge, We, be, mask);  // 0
    cudaEventRecord(evB, s1);
    build_w2_tile<<<dim3(6, 12), 256, 0, s1>>>(Wke, Weo);                // 1
    build_b2_par<<<24, 256, 0, s1>>>(bke, Weo, beo);                     // 2

    // QKV projections — API launch index 3 (ncu capture target)
    {
        GArgs a;
        a.K = 768; a.K1 = 768; a.lda = 768;
        a.g[0] = GArg{Q,   Wq, Wq, bq, (float*)pq};
        a.g[1] = GArg{Kin, Wk, Wk, bk, (float*)pk};
        a.g[2] = GArg{V,   Wv, Wv, bv, (float*)pv};
        gemm_nn<true><<<dim3(6, 16, 3), 256, GNN_SMEM>>>(a);             // 3
    }

    build_b3_par<<<24, 256, 0, s1>>>(Wo + 768 * 768, bo);                // 4
    {
        GArgs a;
        a.K = 768; a.K1 = 768; a.lda = 768;
        a.g[0] = GArg{(const float*)pW2, Wo + 768 * 768, Wo, nullptr, (float*)pW3};
        a.g[1] = a.g[0]; a.g[2] = a.g[0];
        gemm_nn<false><<<dim3(6, 6, 1), 256, GNN_SMEM, s1>>>(a);         // 5: W3 = W2@Wo2
    }
    cudaEventRecord(evE, s1);

    // Fused attention (needs eb+mask)
    cudaStreamWaitEvent(0, evB, 0);
    attn_fused<<<dim3(16, B_ * H_), 256, ATTN_SMEM>>>();                 // 6
    cudaEventRecord(evC, 0);

    // ae on side stream (needs g_attn)
    cudaStreamWaitEvent(s1, evC, 0);
    ae_kernel<<<B_ * L_, 256, 0, s1>>>(edge);                            // 7
    cudaEventRecord(evD, s1);

    // final1: out = ctx @ Wo1 + b3  (overlaps ae)
    cudaStreamWaitEvent(0, evE, 0);
    {
        GArgs a;
        a.K = 768; a.K1 = 768; a.lda = 1536;
        a.g[0] = GArg{(const float*)pcat, Wo, Wo, (const float*)pb3, out};
        a.g[1] = a.g[0]; a.g[2] = a.g[0];
        gemm_nn64<true, false><<<dim3(6, 32, 1), 128>>>(a);              // 8
    }

    // final2: out += ae @ W3
    cudaStreamWaitEvent(0, evD, 0);
    {
        GArgs a;
        a.K = 768; a.K1 = 768; a.lda = 1536;
        a.g[0] = GArg{(const float*)pcat + 768, (const float*)pW3, (const float*)pW3, nullptr, out};
        a.g[1] = a.g[0]; a.g[2] = a.g[0];
        gemm_nn64<false, true><<<dim3(6, 32, 1), 128>>>(a);              // 9
    }
}

// round 10
// speedup vs baseline: 1.0476x; 1.0476x over previous
#include <cuda_runtime.h>
#include <math.h>
#include <stdint.h>

constexpr int B_  = 4;
constexpr int L_  = 512;
constexpr int D_  = 768;
constexpr int H_  = 12;
constexpr int M_  = B_ * L_;
constexpr float SCALE_    = 0.08838834764831845f;
constexpr float INVSQRT2_ = 0.70710678118654752f;
constexpr float CAP_      = 5.0f;

// Scratch
__device__ float g_q   [M_ * D_];
__device__ float g_k   [M_ * D_];
__device__ float g_v   [M_ * D_];
__device__ float g_eb  [B_ * L_ * L_];                // eb with mask folded in
__device__ float g_attn[(size_t)B_ * H_ * L_ * L_];
__device__ float g_cat [M_ * 2 * D_];
__device__ float g_W2  [D_ * D_];
__device__ float g_W3  [D_ * D_];
__device__ float g_b2  [D_];
__device__ float g_b3  [D_];

// ----------------------------------------------------------------------------
// helpers
// ----------------------------------------------------------------------------
__device__ __forceinline__ unsigned f2tf(float x) {
    unsigned u;
    asm("cvt.rna.tf32.f32 %0, %1;" : "=r"(u) : "f"(x));
    return u;
}
__device__ __forceinline__ unsigned cvt_u(unsigned x) {
    return f2tf(__uint_as_float(x));
}
__device__ __forceinline__ void mma8(float* c, const unsigned* a, const unsigned* b) {
    asm volatile(
        "mma.sync.aligned.m16n8k8.row.col.f32.tf32.tf32.f32 "
        "{%0,%1,%2,%3}, {%4,%5,%6,%7}, {%8,%9}, {%0,%1,%2,%3};"
        : "+f"(c[0]), "+f"(c[1]), "+f"(c[2]), "+f"(c[3])
        : "r"(a[0]), "r"(a[1]), "r"(a[2]), "r"(a[3]), "r"(b[0]), "r"(b[1]));
}
__device__ __forceinline__ unsigned smem_u32(const void* p) {
    return (unsigned)__cvta_generic_to_shared(p);
}
__device__ __forceinline__ void ldsm4(unsigned* r, unsigned a) {
    asm volatile("ldmatrix.sync.aligned.m8n8.x4.shared.b16 {%0,%1,%2,%3}, [%4];"
        : "=r"(r[0]), "=r"(r[1]), "=r"(r[2]), "=r"(r[3]) : "r"(a));
}
__device__ __forceinline__ void cp16(unsigned dst, const void* src) {
    asm volatile("cp.async.cg.shared.global [%0], [%1], 16;" :: "r"(dst), "l"(src));
}
__device__ __forceinline__ void cp_commit() {
    asm volatile("cp.async.commit_group;");
}
template<int N>
__device__ __forceinline__ void cp_wait() {
    asm volatile("cp.async.wait_group %0;" :: "n"(N));
}

struct GArg  { const float* A; const float* Bm; const float* B2; const float* bias; float* C; };
struct GArgs { GArg g[3]; int K; int K1; int lda; };

// ----------------------------------------------------------------------------
// NN tf32 GEMM: BM=128 BN=128 BK=16, 256 threads, cp.async 3-stage (R9,
// measured 61.0us on QKV). Dynamic smem 56832 B. Requires (K/16)%3==0.
// ----------------------------------------------------------------------------
constexpr int GNN_SMEM = (3 * 128 * 20 + 3 * 16 * 136) * 4;   // 56832

template<bool BIAS>
__global__ void __launch_bounds__(256, 2) gemm_nn(GArgs args)
{
    extern __shared__ unsigned dyn[];
    unsigned* Asb[3] = { dyn, dyn + 2560, dyn + 5120 };
    unsigned* Bsb[3] = { dyn + 7680, dyn + 7680 + 2176, dyn + 7680 + 4352 };

    const GArg ga = args.g[blockIdx.z];
    const int K  = args.K;
    const int K1 = args.K1;
    const int T  = K >> 4;

    const int tid  = threadIdx.x;
    const int lane = tid & 31;
    const int wid  = tid >> 5;
    const int grp  = lane >> 2;
    const int tig  = lane & 3;
    const int wm0  = (wid >> 1) * 32;
    const int wn0  = (wid & 1) * 64;
    const int m0   = blockIdx.y * 128;
    const int n0   = blockIdx.x * 128;

    float acc[2][8][4];
#pragma unroll
    for (int i = 0; i < 2; i++)
#pragma unroll
        for (int j = 0; j < 8; j++)
#pragma unroll
            for (int q = 0; q < 4; q++) acc[i][j][q] = 0.f;

    const int a_r = tid >> 1, a_c = (tid & 1) * 8;
    const int b_r = tid >> 4, b_c = (tid & 15) * 8;
    const float* Agbase = ga.A + (size_t)(m0 + a_r) * K + a_c;
    const unsigned a_off = (unsigned)((a_r * 20 + a_c) * 4);
    const unsigned b_off = (unsigned)((b_r * 136 + b_c) * 4);

    const int lrow = wm0 + (lane & 7) + 8 * ((lane >> 3) & 1);
    const int lcol = 4 * (lane >> 4);
    unsigned abf[3];
#pragma unroll
    for (int i = 0; i < 3; i++)
        abf[i] = smem_u32(Asb[i]) + (unsigned)((lrow * 20 + lcol) * 4);
    unsigned asd[3], bsd[3];
#pragma unroll
    for (int i = 0; i < 3; i++) { asd[i] = smem_u32(Asb[i]); bsd[i] = smem_u32(Bsb[i]); }

    auto cp_tile = [&](int it, int buf) {
        const int kk = it * 16;
        const float* as = Agbase + kk;
        cp16(asd[buf] + a_off, as);
        cp16(asd[buf] + a_off + 16, as + 4);
        const int krow = kk + b_r;
        const float* bsrc = (krow < K1 ? ga.Bm + (size_t)krow * 768
                                       : ga.B2 + (size_t)(krow - K1) * 768) + n0 + b_c;
        cp16(bsd[buf] + b_off, bsrc);
        cp16(bsd[buf] + b_off + 16, bsrc + 4);
    };

    auto mma_tile = [&](int buf) {
        const unsigned abase = abf[buf];
        const unsigned* Bp = Bsb[buf];
#pragma unroll
        for (int kc = 0; kc < 16; kc += 8) {
            unsigned af[2][4];
            ldsm4(af[0], abase + (unsigned)(kc * 4));
            ldsm4(af[1], abase + (unsigned)((16 * 20 + kc) * 4));
#pragma unroll
            for (int i = 0; i < 2; i++)
#pragma unroll
                for (int q = 0; q < 4; q++) af[i][q] = cvt_u(af[i][q]);
            unsigned bf[8][2];
#pragma unroll
            for (int j = 0; j < 8; j++) {
                bf[j][0] = cvt_u(Bp[(kc + tig) * 136 + wn0 + j * 8 + grp]);
                bf[j][1] = cvt_u(Bp[(kc + tig + 4) * 136 + wn0 + j * 8 + grp]);
            }
#pragma unroll
            for (int i = 0; i < 2; i++)
#pragma unroll
                for (int j = 0; j < 8; j++) mma8(acc[i][j], af[i], bf[j]);
        }
    };

    cp_tile(0, 0); cp_commit();
    cp_tile(1, 1); cp_commit();

    for (int it = 0; it < T; it += 3) {
        cp_wait<1>(); __syncthreads();
        if (it + 2 < T) cp_tile(it + 2, 2);
        cp_commit();
        mma_tile(0);

        cp_wait<1>(); __syncthreads();
        if (it + 3 < T) cp_tile(it + 3, 0);
        cp_commit();
        mma_tile(1);

        cp_wait<1>(); __syncthreads();
        if (it + 4 < T) cp_tile(it + 4, 1);
        cp_commit();
        mma_tile(2);
    }

#pragma unroll
    for (int i = 0; i < 2; i++) {
        int r0 = m0 + wm0 + i * 16 + grp;
#pragma unroll
        for (int j = 0; j < 8; j++) {
            int c = n0 + wn0 + j * 8 + 2 * tig;
            float b0 = 0.f, b1 = 0.f;
            if (BIAS) { b0 = ga.bias[c]; b1 = ga.bias[c + 1]; }
            *(float2*)&ga.C[(size_t)r0 * 768 + c] =
                make_float2(acc[i][j][0] + b0, acc[i][j][1] + b1);
            *(float2*)&ga.C[(size_t)(r0 + 8) * 768 + c] =
                make_float2(acc[i][j][2] + b0, acc[i][j][3] + b1);
        }
    }
}

// ----------------------------------------------------------------------------
// NN tf32 GEMM: BM=64 BN=128, 128 thr, cp.async 3-stage (unchanged).
// ----------------------------------------------------------------------------
template<bool BIAS, bool ACC>
__global__ void __launch_bounds__(128, 3) gemm_nn64(GArgs args)
{
    const GArg ga = args.g[blockIdx.z];
    const int K   = args.K;
    const int K1  = args.K1;
    const int lda = args.lda;
    const int T   = K >> 4;

    __shared__ alignas(16) unsigned As[3][64 * 20];
    __shared__ alignas(16) unsigned Bs[3][16 * 136];

    const int tid  = threadIdx.x;
    const int lane = tid & 31;
    const int wid  = tid >> 5;
    const int grp  = lane >> 2;
    const int tig  = lane & 3;
    const int wm0  = (wid >> 1) * 32;
    const int wn0  = (wid & 1) * 64;
    const int m0   = blockIdx.y * 64;
    const int n0   = blockIdx.x * 128;

    float acc[2][8][4];
#pragma unroll
    for (int i = 0; i < 2; i++)
#pragma unroll
        for (int j = 0; j < 8; j++)
#pragma unroll
            for (int q = 0; q < 4; q++) acc[i][j][q] = 0.f;

    const int a_r = tid >> 1;
    const int a_c = (tid & 1) * 8;
    const float* Agbase = ga.A + (size_t)(m0 + a_r) * lda + a_c;
    const unsigned a_off = (unsigned)((a_r * 20 + a_c) * 4);
    const int b_r = tid >> 3;
    const int b_c = (tid & 7) * 16;
    const unsigned b_off = (unsigned)((b_r * 136 + b_c) * 4);

    const int lrow = wm0 + (lane & 7) + 8 * ((lane >> 3) & 1);
    const int lcol = 4 * (lane >> 4);
    const unsigned ab0 = smem_u32(As[0]) + (unsigned)((lrow * 20 + lcol) * 4);
    const unsigned ab1 = smem_u32(As[1]) + (unsigned)((lrow * 20 + lcol) * 4);
    const unsigned ab2 = smem_u32(As[2]) + (unsigned)((lrow * 20 + lcol) * 4);

    auto cp_tile = [&](int it, unsigned adst, unsigned bdst) {
        const int kk = it * 16;
        const float* as = Agbase + kk;
#pragma unroll
        for (int c = 0; c < 2; c++) cp16(adst + a_off + c * 16, as + c * 4);
        const int krow = kk + b_r;
        const float* bsrc = (krow < K1 ? ga.Bm + (size_t)krow * 768
                                       : ga.B2 + (size_t)(krow - K1) * 768) + n0 + b_c;
#pragma unroll
        for (int c = 0; c < 4; c++) cp16(bdst + b_off + c * 16, bsrc + c * 4);
    };

    auto mma_tile = [&](unsigned abase, const unsigned* Bsb) {
#pragma unroll
        for (int kc = 0; kc < 16; kc += 8) {
            unsigned af[2][4];
#pragma unroll
            for (int i = 0; i < 2; i++) {
                ldsm4(af[i], abase + (unsigned)((i * 16 * 20 + kc) * 4));
#pragma unroll
                for (int q = 0; q < 4; q++) af[i][q] = cvt_u(af[i][q]);
            }
            unsigned bf[8][2];
#pragma unroll
            for (int j = 0; j < 8; j++) {
                bf[j][0] = cvt_u(Bsb[(kc + tig) * 136 + wn0 + j * 8 + grp]);
                bf[j][1] = cvt_u(Bsb[(kc + tig + 4) * 136 + wn0 + j * 8 + grp]);
            }
#pragma unroll
            for (int i = 0; i < 2; i++)
#pragma unroll
                for (int j = 0; j < 8; j++) mma8(acc[i][j], af[i], bf[j]);
        }
    };

    const unsigned asd0 = smem_u32(As[0]), asd1 = smem_u32(As[1]), asd2 = smem_u32(As[2]);
    const unsigned bsd0 = smem_u32(Bs[0]), bsd1 = smem_u32(Bs[1]), bsd2 = smem_u32(Bs[2]);

    cp_tile(0, asd0, bsd0); cp_commit();
    cp_tile(1, asd1, bsd1); cp_commit();

    for (int it = 0; it < T; it += 3) {
        cp_wait<1>(); __syncthreads();
        if (it + 2 < T) cp_tile(it + 2, asd2, bsd2);
        cp_commit();
        mma_tile(ab0, Bs[0]);

        cp_wait<1>(); __syncthreads();
        if (it + 3 < T) cp_tile(it + 3, asd0, bsd0);
        cp_commit();
        mma_tile(ab1, Bs[1]);

        cp_wait<1>(); __syncthreads();
        if (it + 4 < T) cp_tile(it + 4, asd1, bsd1);
        cp_commit();
        mma_tile(ab2, Bs[2]);
    }

#pragma unroll
    for (int i = 0; i < 2; i++) {
        int r0 = m0 + wm0 + i * 16 + grp;
#pragma unroll
        for (int j = 0; j < 8; j++) {
            int c = n0 + wn0 + j * 8 + 2 * tig;
            float b0 = 0.f, b1 = 0.f;
            if (BIAS) { b0 = ga.bias[c]; b1 = ga.bias[c + 1]; }
            float2 o0 = make_float2(acc[i][j][0] + b0, acc[i][j][1] + b1);
            float2 o1 = make_float2(acc[i][j][2] + b0, acc[i][j][3] + b1);
            float2* p0 = (float2*)&ga.C[(size_t)r0 * 768 + c];
            float2* p1 = (float2*)&ga.C[(size_t)(r0 + 8) * 768 + c];
            if (ACC) {
                float2 e0 = *p0, e1 = *p1;
                o0.x += e0.x; o0.y += e0.y; o1.x += e1.x; o1.y += e1.y;
            }
            *p0 = o0; *p1 = o1;
        }
    }
}

// ----------------------------------------------------------------------------
// Fused attention (R8 geometry — 64 q-rows, 512 threads, 219136 B smem),
// mask folded into g_eb (no mask loads here).
// ----------------------------------------------------------------------------
constexpr int SC_STRIDE = 516;
constexpr int SC_BYTES  = 64 * SC_STRIDE * 4;        // 132096
constexpr int QS_BYTES  = 64 * 68 * 4;               // 17408
constexpr int KV_BYTES  = 128 * 68 * 4;              // 34816
constexpr int ATTN_SMEM = SC_BYTES + QS_BYTES + 2 * KV_BYTES;  // 219136

__global__ void __launch_bounds__(512, 1) attn_fused()
{
    extern __shared__ char dsm[];
    float*    Sc  = (float*)dsm;                         // 64 x 516
    unsigned* Qs  = (unsigned*)(dsm + SC_BYTES);         // 64 x 68
    unsigned* Kv0 = (unsigned*)(dsm + SC_BYTES + QS_BYTES);
    unsigned* Kv1 = Kv0 + 128 * 68;

    const int bh = blockIdx.y;
    const int b  = bh / H_;
    const int h  = bh % H_;
    const int n0 = blockIdx.x * 64;

    const int tid  = threadIdx.x;
    const int lane = tid & 31;
    const int w    = tid >> 5;          // 0..15
    const int grp  = lane >> 2;
    const int tig  = lane & 3;

    // ---- Phase 1: Q (64x64) tf32 ----
    {
        int row = tid >> 3, col = (tid & 7) * 8;
        const float* src = g_q + (size_t)(b * 512 + n0 + row) * 768 + h * 64 + col;
        float4 q0 = *(const float4*)src;
        float4 q1 = *(const float4*)(src + 4);
        *(uint4*)&Qs[row * 68 + col]     = make_uint4(f2tf(q0.x), f2tf(q0.y), f2tf(q0.z), f2tf(q0.w));
        *(uint4*)&Qs[row * 68 + col + 4] = make_uint4(f2tf(q1.x), f2tf(q1.y), f2tf(q1.z), f2tf(q1.w));
    }

    // chunk staging: 128 rows x 64 cols
    const int srow = tid >> 2;
    const int scol = (tid & 3) * 16;
    float4 st[4];
    auto ldg_chunk = [&](const float* basep, int mc) {
        const float* s = basep + (size_t)(b * 512 + mc + srow) * 768 + h * 64 + scol;
        st[0] = *(const float4*)(s);
        st[1] = *(const float4*)(s + 4);
        st[2] = *(const float4*)(s + 8);
        st[3] = *(const float4*)(s + 12);
    };
    auto sts_chunk = [&](unsigned* buf) {
#pragma unroll
        for (int c = 0; c < 4; c++)
            *(uint4*)&buf[srow * 68 + scol + c * 4] =
                make_uint4(f2tf(st[c].x), f2tf(st[c].y), f2tf(st[c].z), f2tf(st[c].w));
    };

    ldg_chunk(g_k, 0);
    sts_chunk(Kv0);
    __syncthreads();

    // ---- Phase 2: scores over 4 m-chunks ----
    const int qb = (w >> 3) * 32;      // 0 or 32
    const int mb = (w & 7) * 16;       // 0..112
    const unsigned aq0 = smem_u32(Qs) +
        (unsigned)(((qb + (lane & 7) + 8 * ((lane >> 3) & 1)) * 68 + 4 * (lane >> 4)) * 4);
    const unsigned koff =
        (unsigned)(((mb + (lane & 7) + 8 * (lane >> 4)) * 68 + 4 * ((lane >> 3) & 1)) * 4);
    const unsigned kvb[2] = { smem_u32(Kv0), smem_u32(Kv1) };

    for (int c = 0; c < 4; c++) {
        if (c < 3) ldg_chunk(g_k, (c + 1) * 128);
        float acc[2][2][4];
#pragma unroll
        for (int i = 0; i < 2; i++)
#pragma unroll
            for (int j = 0; j < 2; j++)
#pragma unroll
                for (int q = 0; q < 4; q++) acc[i][j][q] = 0.f;

        const unsigned kb = kvb[c & 1] + koff;
#pragma unroll
        for (int kc = 0; kc < 64; kc += 8) {
            unsigned af[2][4];
            ldsm4(af[0], aq0 + (unsigned)(kc * 4));
            ldsm4(af[1], aq0 + (unsigned)((16 * 68 + kc) * 4));
            unsigned t[4];
            ldsm4(t, kb + (unsigned)(kc * 4));
            unsigned bf0[2] = { t[0], t[1] };
            unsigned bf1[2] = { t[2], t[3] };
            mma8(acc[0][0], af[0], bf0); mma8(acc[0][1], af[0], bf1);
            mma8(acc[1][0], af[1], bf0); mma8(acc[1][1], af[1], bf1);
        }

        const int mc = c * 128;
#pragma unroll
        for (int qt = 0; qt < 2; qt++) {
#pragma unroll
            for (int p = 0; p < 2; p++) {
                int row = qb + qt * 16 + grp + p * 8;
#pragma unroll
                for (int mt = 0; mt < 2; mt++) {
                    int col = mc + mb + mt * 8 + 2 * tig;
                    size_t em = (size_t)(b * 512 + n0 + row) * 512 + col;
                    float2 e2 = *(const float2*)&g_eb[em];   // mask pre-folded
                    *(float2*)&Sc[row * SC_STRIDE + col] =
                        make_float2(acc[qt][mt][2 * p]     * SCALE_ + e2.x,
                                    acc[qt][mt][2 * p + 1] * SCALE_ + e2.y);
                }
            }
        }
        if (c < 3) sts_chunk((c & 1) ? Kv0 : Kv1);
        __syncthreads();
    }

    // prefetch V chunk 0 (overlaps softmax)
    ldg_chunk(g_v, 0);

    // ---- Phase 3: softmax in smem; write attn; keep tf32 copy in Sc ----
#pragma unroll
    for (int r = 0; r < 4; r++) {
        int row = w * 4 + r;
        float4 v[4];
#pragma unroll
        for (int j = 0; j < 4; j++)
            v[j] = *(float4*)&Sc[row * SC_STRIDE + lane * 4 + j * 128];
        float mx = -1e30f;
#pragma unroll
        for (int j = 0; j < 4; j++)
            mx = fmaxf(mx, fmaxf(fmaxf(v[j].x, v[j].y), fmaxf(v[j].z, v[j].w)));
#pragma unroll
        for (int o = 16; o > 0; o >>= 1)
            mx = fmaxf(mx, __shfl_xor_sync(0xffffffffu, mx, o));
        float sum = 0.f;
#pragma unroll
        for (int j = 0; j < 4; j++) {
            v[j].x = __expf(v[j].x - mx); v[j].y = __expf(v[j].y - mx);
            v[j].z = __expf(v[j].z - mx); v[j].w = __expf(v[j].w - mx);
            sum += v[j].x + v[j].y + v[j].z + v[j].w;
        }
#pragma unroll
        for (int o = 16; o > 0; o >>= 1)
            sum += __shfl_xor_sync(0xffffffffu, sum, o);
        float inv = 1.0f / sum;
        float4* gout = (float4*)&g_attn[((size_t)bh * 512 + n0 + row) * 512];
#pragma unroll
        for (int j = 0; j < 4; j++) {
            float4 nv = make_float4(v[j].x * inv, v[j].y * inv, v[j].z * inv, v[j].w * inv);
            gout[lane + j * 32] = nv;
            *(uint4*)&Sc[row * SC_STRIDE + lane * 4 + j * 128] =
                make_uint4(f2tf(nv.x), f2tf(nv.y), f2tf(nv.z), f2tf(nv.w));
        }
    }
    sts_chunk(Kv0);
    __syncthreads();

    // ---- Phase 4: ctx = attn @ v ----
    const int db = (w & 7) * 8;
    float acc2[2][4];
#pragma unroll
    for (int i = 0; i < 2; i++)
#pragma unroll
        for (int q = 0; q < 4; q++) acc2[i][q] = 0.f;

    const unsigned as0 = smem_u32(Sc) +
        (unsigned)(((qb + (lane & 7) + 8 * ((lane >> 3) & 1)) * SC_STRIDE + 4 * (lane >> 4)) * 4);

    for (int c = 0; c < 4; c++) {
        if (c < 3) ldg_chunk(g_v, (c + 1) * 128);
        const unsigned* kvu = (c & 1) ? Kv1 : Kv0;
#pragma unroll
        for (int ml = 0; ml < 128; ml += 8) {
            unsigned af[2][4];
            ldsm4(af[0], as0 + (unsigned)((c * 128 + ml) * 4));
            ldsm4(af[1], as0 + (unsigned)((16 * SC_STRIDE + c * 128 + ml) * 4));
            unsigned bf[2];
            bf[0] = kvu[(ml + tig) * 68 + db + grp];
            bf[1] = kvu[(ml + tig + 4) * 68 + db + grp];
            mma8(acc2[0], af[0], bf);
            mma8(acc2[1], af[1], bf);
        }
        if (c < 3) sts_chunk((c & 1) ? Kv0 : Kv1);
        __syncthreads();
    }

#pragma unroll
    for (int qt = 0; qt < 2; qt++) {
#pragma unroll
        for (int p = 0; p < 2; p++) {
            int row = qb + qt * 16 + grp + p * 8;
            int col = h * 64 + db + 2 * tig;
            *(float2*)&g_cat[(size_t)(b * 512 + n0 + row) * 1536 + col] =
                make_float2(acc2[qt][2 * p], acc2[qt][2 * p + 1]);
        }
    }
}

// ----------------------------------------------------------------------------
// Weight folds (side stream)
// ----------------------------------------------------------------------------
__global__ void __launch_bounds__(256) build_w2_tile(
    const float* __restrict__ Wke, const float* __restrict__ Weo)
{
    __shared__ float Ws[64 * 64];
    const int tid = threadIdx.x;
    const int h   = blockIdx.y;
    const int j0  = blockIdx.x * 128;

#pragma unroll
    for (int i = 0; i < 16; i++)
        Ws[tid + i * 256] = Wke[tid + i * 256];
    __syncthreads();

    const int jl = tid & 127;
    const int c0 = (tid >> 7) * 32;
    float acc[32];
#pragma unroll
    for (int c = 0; c < 32; c++) acc[c] = 0.f;

    for (int e = 0; e < 64; e++) {
        float w = Weo[(size_t)(h * 64 + e) * 768 + j0 + jl];
#pragma unroll
        for (int c = 0; c < 32; c++)
            acc[c] += Ws[(c0 + c) * 64 + e] * w;
    }
#pragma unroll
    for (int c = 0; c < 32; c++)
        g_W2[(size_t)(h * 64 + c0 + c) * 768 + j0 + jl] = acc[c];
}

__global__ void __launch_bounds__(256) build_b2_par(
    const float* __restrict__ bke, const float* __restrict__ Weo,
    const float* __restrict__ beo)
{
    __shared__ float red[8][32];
    const int tid = threadIdx.x;
    const int jl  = tid & 31;
    const int rw  = tid >> 5;
    const int j   = blockIdx.x * 32 + jl;

    float acc = 0.f;
    for (int r = rw; r < 768; r += 8)
        acc += bke[r & 63] * Weo[(size_t)r * 768 + j];
    red[rw][jl] = acc;
    __syncthreads();
    if (rw == 0) {
        float s = beo[j];
#pragma unroll
        for (int i = 0; i < 8; i++) s += red[i][jl];
        g_b2[j] = s;
    }
}

__global__ void __launch_bounds__(256) build_b3_par(
    const float* __restrict__ Wo2, const float* __restrict__ bo)
{
    __shared__ float red[8][32];
    const int tid = threadIdx.x;
    const int jl  = tid & 31;
    const int rw  = tid >> 5;
    const int j   = blockIdx.x * 32 + jl;

    float acc = 0.f;
    for (int r = rw; r < 768; r += 8)
        acc += g_b2[r] * Wo2[(size_t)r * 768 + j];
    red[rw][jl] = acc;
    __syncthreads();
    if (rw == 0) {
        float s = bo[j];
#pragma unroll
        for (int i = 0; i < 8; i++) s += red[i][jl];
        g_b3[j] = s;
    }
}

// ----------------------------------------------------------------------------
// Edge bias (softcap) with mask folded
// ----------------------------------------------------------------------------
__global__ void __launch_bounds__(256) eb_kernel(
    const float* __restrict__ edge, const float* __restrict__ We,
    const float* __restrict__ be, const unsigned char* __restrict__ mask)
{
    int idx  = blockIdx.x * 16 + (threadIdx.x >> 4);
    int l16  = threadIdx.x & 15;
    const float4 e4 = *(const float4*)(edge + (size_t)idx * 64 + l16 * 4);
    const float4 w4 = *(const float4*)(We + l16 * 4);
    float acc = e4.x * w4.x + e4.y * w4.y + e4.z * w4.z + e4.w * w4.w;
#pragma unroll
    for (int o = 8; o > 0; o >>= 1)
        acc += __shfl_xor_sync(0xffffffffu, acc, o);
    if (l16 == 0) {
        float x = (acc + be[0]) * INVSQRT2_;
        float r = CAP_ * tanhf(x * (1.0f / CAP_));
        g_eb[idx] = mask[idx] ? -1e9f : r;
    }
}

// ----------------------------------------------------------------------------
// ae -> g_cat[:, 768:1536]
// ----------------------------------------------------------------------------
__global__ void __launch_bounds__(256) ae_kernel(const float* __restrict__ edge)
{
    const int bn = blockIdx.x;
    const int b  = bn >> 9;
    const int n  = bn & 511;

    __shared__ float Es[64 * 64];
    __shared__ float Asm[12 * 64];

    const int tid = threadIdx.x;
    const int d   = tid & 63;
    const int h0  = tid >> 6;

    float acc0 = 0.f, acc1 = 0.f, acc2 = 0.f;
    const float* ebase = edge + (size_t)bn * 512 * 64;

    for (int mc = 0; mc < 512; mc += 64) {
        const float4* eg = (const float4*)(ebase + (size_t)mc * 64);
        float4* es4 = (float4*)Es;
#pragma unroll
        for (int i = 0; i < 4; i++)
            es4[tid + i * 256] = eg[tid + i * 256];
#pragma unroll
        for (int i = 0; i < 3; i++) {
            int lin = tid + i * 256;
            int hh = lin >> 6, mm = lin & 63;
            Asm[lin] = g_attn[(((size_t)(b * H_ + hh)) * 512 + n) * 512 + mc + mm];
        }
        __syncthreads();
#pragma unroll 4
        for (int m = 0; m < 64; m += 4) {
            float4 a0 = *(const float4*)&Asm[(h0    ) * 64 + m];
            float4 a1 = *(const float4*)&Asm[(h0 + 4) * 64 + m];
            float4 a2 = *(const float4*)&Asm[(h0 + 8) * 64 + m];
            float e0 = Es[(m + 0) * 64 + d];
            float e1 = Es[(m + 1) * 64 + d];
            float e2 = Es[(m + 2) * 64 + d];
            float e3 = Es[(m + 3) * 64 + d];
            acc0 += a0.x * e0 + a0.y * e1 + a0.z * e2 + a0.w * e3;
            acc1 += a1.x * e0 + a1.y * e1 + a1.z * e2 + a1.w * e3;
            acc2 += a2.x * e0 + a2.y * e1 + a2.z * e2 + a2.w * e3;
        }
        __syncthreads();
    }

    float* ar = g_cat + (size_t)bn * 1536 + 768;
    ar[(h0    ) * 64 + d] = acc0;
    ar[(h0 + 4) * 64 + d] = acc1;
    ar[(h0 + 8) * 64 + d] = acc2;
}

// ----------------------------------------------------------------------------
// Launch. Critical: QKV(idx 3) -> attn_fused -> final1 -> final2.
// Side s1: eb(+mask), folds, W3, ae.
// ----------------------------------------------------------------------------
extern "C" void kernel_launch(void* const* d_in, const int* in_sizes, int n_in,
                              void* d_out, int out_size)
{
    const float* Q    = (const float*)d_in[0];
    const float* Kin  = (const float*)d_in[1];
    const float* V    = (const float*)d_in[2];
    const unsigned char* mask = (const unsigned char*)d_in[3];
    const float* edge = (const float*)d_in[4];
    const float* Wq   = (const float*)d_in[5];
    const float* bq   = (const float*)d_in[6];
    const float* Wk   = (const float*)d_in[7];
    const float* bk   = (const float*)d_in[8];
    const float* Wv   = (const float*)d_in[9];
    const float* bv   = (const float*)d_in[10];
    const float* Wke  = (const float*)d_in[11];
    const float* bke  = (const float*)d_in[12];
    const float* We   = (const float*)d_in[13];
    const float* be   = (const float*)d_in[14];
    const float* Weo  = (const float*)d_in[15];
    const float* beo  = (const float*)d_in[16];
    const float* Wo   = (const float*)d_in[17];
    const float* bo   = (const float*)d_in[18];
    float* out = (float*)d_out;

    void *pq, *pk, *pv, *pcat, *pW2, *pW3, *pb3;
    cudaGetSymbolAddress(&pq,   g_q);
    cudaGetSymbolAddress(&pk,   g_k);
    cudaGetSymbolAddress(&pv,   g_v);
    cudaGetSymbolAddress(&pcat, g_cat);
    cudaGetSymbolAddress(&pW2,  g_W2);
    cudaGetSymbolAddress(&pW3,  g_W3);
    cudaGetSymbolAddress(&pb3,  g_b3);

    static cudaStream_t s1 = nullptr;
    static cudaEvent_t evA = nullptr, evB = nullptr, evC = nullptr, evD = nullptr, evE = nullptr;
    if (!s1) {
        cudaStreamCreateWithFlags(&s1, cudaStreamNonBlocking);
        cudaEventCreateWithFlags(&evA, cudaEventDisableTiming);
        cudaEventCreateWithFlags(&evB, cudaEventDisableTiming);
        cudaEventCreateWithFlags(&evC, cudaEventDisableTiming);
        cudaEventCreateWithFlags(&evD, cudaEventDisableTiming);
        cudaEventCreateWithFlags(&evE, cudaEventDisableTiming);
        cudaFuncSetAttribute(attn_fused, cudaFuncAttributeMaxDynamicSharedMemorySize, ATTN_SMEM);
        cudaFuncSetAttribute(gemm_nn<true>,  cudaFuncAttributeMaxDynamicSharedMemorySize, GNN_SMEM);
        cudaFuncSetAttribute(gemm_nn<false>, cudaFuncAttributeMaxDynamicSharedMemorySize, GNN_SMEM);
    }

    cudaEventRecord(evA, 0);
    cudaStreamWaitEvent(s1, evA, 0);

    eb_kernel<<<(B_ * L_ * L_) / 16, 256, 0, s1>>>(edge, We, be, mask);  // 0
    cudaEventRecord(evB, s1);
    build_w2_tile<<<dim3(6, 12), 256, 0, s1>>>(Wke, Weo);                // 1
    build_b2_par<<<24, 256, 0, s1>>>(bke, Weo, beo);                     // 2

    // QKV projections — API launch index 3 (ncu capture target)
    {
        GArgs a;
        a.K = 768; a.K1 = 768; a.lda = 768;
        a.g[0] = GArg{Q,   Wq, Wq, bq, (float*)pq};
        a.g[1] = GArg{Kin, Wk, Wk, bk, (float*)pk};
        a.g[2] = GArg{V,   Wv, Wv, bv, (float*)pv};
        gemm_nn<true><<<dim3(6, 16, 3), 256, GNN_SMEM>>>(a);             // 3
    }

    build_b3_par<<<24, 256, 0, s1>>>(Wo + 768 * 768, bo);                // 4
    {
        GArgs a;
        a.K = 768; a.K1 = 768; a.lda = 768;
        a.g[0] = GArg{(const float*)pW2, Wo + 768 * 768, Wo, nullptr, (float*)pW3};
        a.g[1] = a.g[0]; a.g[2] = a.g[0];
        gemm_nn<false><<<dim3(6, 6, 1), 256, GNN_SMEM, s1>>>(a);         // 5: W3 = W2@Wo2
    }
    cudaEventRecord(evE, s1);

    // Fused attention (needs eb with mask folded)
    cudaStreamWaitEvent(0, evB, 0);
    attn_fused<<<dim3(8, B_ * H_), 512, ATTN_SMEM>>>();                  // 6
    cudaEventRecord(evC, 0);

    // ae on side stream (needs g_attn)
    cudaStreamWaitEvent(s1, evC, 0);
    ae_kernel<<<B_ * L_, 256, 0, s1>>>(edge);                            // 7
    cudaEventRecord(evD, s1);

    // final1: out = ctx @ Wo1 + b3  (overlaps ae)
    cudaStreamWaitEvent(0, evE, 0);
    {
        GArgs a;
        a.K = 768; a.K1 = 768; a.lda = 1536;
        a.g[0] = GArg{(const float*)pcat, Wo, Wo, (const float*)pb3, out};
        a.g[1] = a.g[0]; a.g[2] = a.g[0];
        gemm_nn64<true, false><<<dim3(6, 32, 1), 128>>>(a);              // 8
    }

    // final2: out += ae @ W3
    cudaStreamWaitEvent(0, evD, 0);
    {
        GArgs a;
        a.K = 768; a.K1 = 768; a.lda = 1536;
        a.g[0] = GArg{(const float*)pcat + 768, (const float*)pW3, (const float*)pW3, nullptr, out};
        a.g[1] = a.g[0]; a.g[2] = a.g[0];
        gemm_nn64<false, true><<<dim3(6, 32, 1), 128>>>(a);              // 9
    }
}

// round 11
// speedup vs baseline: 1.0753x; 1.0265x over previous
#include <cuda_runtime.h>
#include <math.h>
#include <stdint.h>

constexpr int B_  = 4;
constexpr int L_  = 512;
constexpr int D_  = 768;
constexpr int H_  = 12;
constexpr int M_  = B_ * L_;
constexpr float SCALE_    = 0.08838834764831845f;
constexpr float INVSQRT2_ = 0.70710678118654752f;
constexpr float CAP_      = 5.0f;

// Scratch
__device__ float g_q   [M_ * D_];
__device__ float g_k   [M_ * D_];
__device__ float g_v   [M_ * D_];
__device__ float g_eb  [B_ * L_ * L_];                // eb with mask folded in
__device__ float g_attn[(size_t)B_ * H_ * L_ * L_];
__device__ float g_cat [M_ * 2 * D_];
__device__ float g_W2  [D_ * D_];
__device__ float g_W3  [D_ * D_];
__device__ float g_b2  [D_];
__device__ float g_b3  [D_];

// ----------------------------------------------------------------------------
// helpers
// ----------------------------------------------------------------------------
__device__ __forceinline__ unsigned f2tf(float x) {
    unsigned u;
    asm("cvt.rna.tf32.f32 %0, %1;" : "=r"(u) : "f"(x));
    return u;
}
__device__ __forceinline__ unsigned cvt_u(unsigned x) {
    return f2tf(__uint_as_float(x));
}
__device__ __forceinline__ void mma8(float* c, const unsigned* a, const unsigned* b) {
    asm volatile(
        "mma.sync.aligned.m16n8k8.row.col.f32.tf32.tf32.f32 "
        "{%0,%1,%2,%3}, {%4,%5,%6,%7}, {%8,%9}, {%0,%1,%2,%3};"
        : "+f"(c[0]), "+f"(c[1]), "+f"(c[2]), "+f"(c[3])
        : "r"(a[0]), "r"(a[1]), "r"(a[2]), "r"(a[3]), "r"(b[0]), "r"(b[1]));
}
__device__ __forceinline__ unsigned smem_u32(const void* p) {
    return (unsigned)__cvta_generic_to_shared(p);
}
__device__ __forceinline__ void ldsm4(unsigned* r, unsigned a) {
    asm volatile("ldmatrix.sync.aligned.m8n8.x4.shared.b16 {%0,%1,%2,%3}, [%4];"
        : "=r"(r[0]), "=r"(r[1]), "=r"(r[2]), "=r"(r[3]) : "r"(a));
}
__device__ __forceinline__ void cp16(unsigned dst, const void* src) {
    asm volatile("cp.async.cg.shared.global [%0], [%1], 16;" :: "r"(dst), "l"(src));
}
__device__ __forceinline__ void cp_commit() {
    asm volatile("cp.async.commit_group;");
}
template<int N>
__device__ __forceinline__ void cp_wait() {
    asm volatile("cp.async.wait_group %0;" :: "n"(N));
}

struct GArg  { const float* A; const float* Bm; const float* B2; const float* bias; float* C; };
struct GArgs { GArg g[3]; int K; int K1; int lda; };

// ----------------------------------------------------------------------------
// NN tf32 GEMM: BM=128 BN=128 BK=16, 256 threads, cp.async 3-stage
// (measured 61us on QKV). Dynamic smem 56832 B. Requires (K/16)%3==0.
// ----------------------------------------------------------------------------
constexpr int GNN_SMEM = (3 * 128 * 20 + 3 * 16 * 136) * 4;   // 56832

template<bool BIAS>
__global__ void __launch_bounds__(256, 2) gemm_nn(GArgs args)
{
    extern __shared__ unsigned dyn[];
    unsigned* Asb[3] = { dyn, dyn + 2560, dyn + 5120 };
    unsigned* Bsb[3] = { dyn + 7680, dyn + 7680 + 2176, dyn + 7680 + 4352 };

    const GArg ga = args.g[blockIdx.z];
    const int K  = args.K;
    const int K1 = args.K1;
    const int T  = K >> 4;

    const int tid  = threadIdx.x;
    const int lane = tid & 31;
    const int wid  = tid >> 5;
    const int grp  = lane >> 2;
    const int tig  = lane & 3;
    const int wm0  = (wid >> 1) * 32;
    const int wn0  = (wid & 1) * 64;
    const int m0   = blockIdx.y * 128;
    const int n0   = blockIdx.x * 128;

    float acc[2][8][4];
#pragma unroll
    for (int i = 0; i < 2; i++)
#pragma unroll
        for (int j = 0; j < 8; j++)
#pragma unroll
            for (int q = 0; q < 4; q++) acc[i][j][q] = 0.f;

    const int a_r = tid >> 1, a_c = (tid & 1) * 8;
    const int b_r = tid >> 4, b_c = (tid & 15) * 8;
    const float* Agbase = ga.A + (size_t)(m0 + a_r) * K + a_c;
    const unsigned a_off = (unsigned)((a_r * 20 + a_c) * 4);
    const unsigned b_off = (unsigned)((b_r * 136 + b_c) * 4);

    const int lrow = wm0 + (lane & 7) + 8 * ((lane >> 3) & 1);
    const int lcol = 4 * (lane >> 4);
    unsigned abf[3];
#pragma unroll
    for (int i = 0; i < 3; i++)
        abf[i] = smem_u32(Asb[i]) + (unsigned)((lrow * 20 + lcol) * 4);
    unsigned asd[3], bsd[3];
#pragma unroll
    for (int i = 0; i < 3; i++) { asd[i] = smem_u32(Asb[i]); bsd[i] = smem_u32(Bsb[i]); }

    auto cp_tile = [&](int it, int buf) {
        const int kk = it * 16;
        const float* as = Agbase + kk;
        cp16(asd[buf] + a_off, as);
        cp16(asd[buf] + a_off + 16, as + 4);
        const int krow = kk + b_r;
        const float* bsrc = (krow < K1 ? ga.Bm + (size_t)krow * 768
                                       : ga.B2 + (size_t)(krow - K1) * 768) + n0 + b_c;
        cp16(bsd[buf] + b_off, bsrc);
        cp16(bsd[buf] + b_off + 16, bsrc + 4);
    };

    auto mma_tile = [&](int buf) {
        const unsigned abase = abf[buf];
        const unsigned* Bp = Bsb[buf];
#pragma unroll
        for (int kc = 0; kc < 16; kc += 8) {
            unsigned af[2][4];
            ldsm4(af[0], abase + (unsigned)(kc * 4));
            ldsm4(af[1], abase + (unsigned)((16 * 20 + kc) * 4));
#pragma unroll
            for (int i = 0; i < 2; i++)
#pragma unroll
                for (int q = 0; q < 4; q++) af[i][q] = cvt_u(af[i][q]);
            unsigned bf[8][2];
#pragma unroll
            for (int j = 0; j < 8; j++) {
                bf[j][0] = cvt_u(Bp[(kc + tig) * 136 + wn0 + j * 8 + grp]);
                bf[j][1] = cvt_u(Bp[(kc + tig + 4) * 136 + wn0 + j * 8 + grp]);
            }
#pragma unroll
            for (int i = 0; i < 2; i++)
#pragma unroll
                for (int j = 0; j < 8; j++) mma8(acc[i][j], af[i], bf[j]);
        }
    };

    cp_tile(0, 0); cp_commit();
    cp_tile(1, 1); cp_commit();

    for (int it = 0; it < T; it += 3) {
        cp_wait<1>(); __syncthreads();
        if (it + 2 < T) cp_tile(it + 2, 2);
        cp_commit();
        mma_tile(0);

        cp_wait<1>(); __syncthreads();
        if (it + 3 < T) cp_tile(it + 3, 0);
        cp_commit();
        mma_tile(1);

        cp_wait<1>(); __syncthreads();
        if (it + 4 < T) cp_tile(it + 4, 1);
        cp_commit();
        mma_tile(2);
    }

#pragma unroll
    for (int i = 0; i < 2; i++) {
        int r0 = m0 + wm0 + i * 16 + grp;
#pragma unroll
        for (int j = 0; j < 8; j++) {
            int c = n0 + wn0 + j * 8 + 2 * tig;
            float b0 = 0.f, b1 = 0.f;
            if (BIAS) { b0 = ga.bias[c]; b1 = ga.bias[c + 1]; }
            *(float2*)&ga.C[(size_t)r0 * 768 + c] =
                make_float2(acc[i][j][0] + b0, acc[i][j][1] + b1);
            *(float2*)&ga.C[(size_t)(r0 + 8) * 768 + c] =
                make_float2(acc[i][j][2] + b0, acc[i][j][3] + b1);
        }
    }
}

// ----------------------------------------------------------------------------
// NN tf32 GEMM: BM=64 BN=128, 128 thr, cp.async 3-stage (unchanged).
// ----------------------------------------------------------------------------
template<bool BIAS, bool ACC>
__global__ void __launch_bounds__(128, 3) gemm_nn64(GArgs args)
{
    const GArg ga = args.g[blockIdx.z];
    const int K   = args.K;
    const int K1  = args.K1;
    const int lda = args.lda;
    const int T   = K >> 4;

    __shared__ alignas(16) unsigned As[3][64 * 20];
    __shared__ alignas(16) unsigned Bs[3][16 * 136];

    const int tid  = threadIdx.x;
    const int lane = tid & 31;
    const int wid  = tid >> 5;
    const int grp  = lane >> 2;
    const int tig  = lane & 3;
    const int wm0  = (wid >> 1) * 32;
    const int wn0  = (wid & 1) * 64;
    const int m0   = blockIdx.y * 64;
    const int n0   = blockIdx.x * 128;

    float acc[2][8][4];
#pragma unroll
    for (int i = 0; i < 2; i++)
#pragma unroll
        for (int j = 0; j < 8; j++)
#pragma unroll
            for (int q = 0; q < 4; q++) acc[i][j][q] = 0.f;

    const int a_r = tid >> 1;
    const int a_c = (tid & 1) * 8;
    const float* Agbase = ga.A + (size_t)(m0 + a_r) * lda + a_c;
    const unsigned a_off = (unsigned)((a_r * 20 + a_c) * 4);
    const int b_r = tid >> 3;
    const int b_c = (tid & 7) * 16;
    const unsigned b_off = (unsigned)((b_r * 136 + b_c) * 4);

    const int lrow = wm0 + (lane & 7) + 8 * ((lane >> 3) & 1);
    const int lcol = 4 * (lane >> 4);
    const unsigned ab0 = smem_u32(As[0]) + (unsigned)((lrow * 20 + lcol) * 4);
    const unsigned ab1 = smem_u32(As[1]) + (unsigned)((lrow * 20 + lcol) * 4);
    const unsigned ab2 = smem_u32(As[2]) + (unsigned)((lrow * 20 + lcol) * 4);

    auto cp_tile = [&](int it, unsigned adst, unsigned bdst) {
        const int kk = it * 16;
        const float* as = Agbase + kk;
#pragma unroll
        for (int c = 0; c < 2; c++) cp16(adst + a_off + c * 16, as + c * 4);
        const int krow = kk + b_r;
        const float* bsrc = (krow < K1 ? ga.Bm + (size_t)krow * 768
                                       : ga.B2 + (size_t)(krow - K1) * 768) + n0 + b_c;
#pragma unroll
        for (int c = 0; c < 4; c++) cp16(bdst + b_off + c * 16, bsrc + c * 4);
    };

    auto mma_tile = [&](unsigned abase, const unsigned* Bsb) {
#pragma unroll
        for (int kc = 0; kc < 16; kc += 8) {
            unsigned af[2][4];
#pragma unroll
            for (int i = 0; i < 2; i++) {
                ldsm4(af[i], abase + (unsigned)((i * 16 * 20 + kc) * 4));
#pragma unroll
                for (int q = 0; q < 4; q++) af[i][q] = cvt_u(af[i][q]);
            }
            unsigned bf[8][2];
#pragma unroll
            for (int j = 0; j < 8; j++) {
                bf[j][0] = cvt_u(Bsb[(kc + tig) * 136 + wn0 + j * 8 + grp]);
                bf[j][1] = cvt_u(Bsb[(kc + tig + 4) * 136 + wn0 + j * 8 + grp]);
            }
#pragma unroll
            for (int i = 0; i < 2; i++)
#pragma unroll
                for (int j = 0; j < 8; j++) mma8(acc[i][j], af[i], bf[j]);
        }
    };

    const unsigned asd0 = smem_u32(As[0]), asd1 = smem_u32(As[1]), asd2 = smem_u32(As[2]);
    const unsigned bsd0 = smem_u32(Bs[0]), bsd1 = smem_u32(Bs[1]), bsd2 = smem_u32(Bs[2]);

    cp_tile(0, asd0, bsd0); cp_commit();
    cp_tile(1, asd1, bsd1); cp_commit();

    for (int it = 0; it < T; it += 3) {
        cp_wait<1>(); __syncthreads();
        if (it + 2 < T) cp_tile(it + 2, asd2, bsd2);
        cp_commit();
        mma_tile(ab0, Bs[0]);

        cp_wait<1>(); __syncthreads();
        if (it + 3 < T) cp_tile(it + 3, asd0, bsd0);
        cp_commit();
        mma_tile(ab1, Bs[1]);

        cp_wait<1>(); __syncthreads();
        if (it + 4 < T) cp_tile(it + 4, asd1, bsd1);
        cp_commit();
        mma_tile(ab2, Bs[2]);
    }

#pragma unroll
    for (int i = 0; i < 2; i++) {
        int r0 = m0 + wm0 + i * 16 + grp;
#pragma unroll
        for (int j = 0; j < 8; j++) {
            int c = n0 + wn0 + j * 8 + 2 * tig;
            float b0 = 0.f, b1 = 0.f;
            if (BIAS) { b0 = ga.bias[c]; b1 = ga.bias[c + 1]; }
            float2 o0 = make_float2(acc[i][j][0] + b0, acc[i][j][1] + b1);
            float2 o1 = make_float2(acc[i][j][2] + b0, acc[i][j][3] + b1);
            float2* p0 = (float2*)&ga.C[(size_t)r0 * 768 + c];
            float2* p1 = (float2*)&ga.C[(size_t)(r0 + 8) * 768 + c];
            if (ACC) {
                float2 e0 = *p0, e1 = *p1;
                o0.x += e0.x; o0.y += e0.y; o1.x += e1.x; o1.y += e1.y;
            }
            *p0 = o0; *p1 = o1;
        }
    }
}

// ----------------------------------------------------------------------------
// Fused attention (64 q-rows, 512 threads) — K/V chunks now via cp.async
// (raw fp32 in smem, cvt at consume). One __syncthreads per chunk.
// ----------------------------------------------------------------------------
constexpr int SC_STRIDE = 516;
constexpr int SC_BYTES  = 64 * SC_STRIDE * 4;        // 132096
constexpr int QS_BYTES  = 64 * 68 * 4;               // 17408
constexpr int KV_BYTES  = 128 * 68 * 4;              // 34816
constexpr int ATTN_SMEM = SC_BYTES + QS_BYTES + 2 * KV_BYTES;  // 219136

__global__ void __launch_bounds__(512, 1) attn_fused()
{
    extern __shared__ char dsm[];
    float*    Sc  = (float*)dsm;                         // 64 x 516
    unsigned* Qs  = (unsigned*)(dsm + SC_BYTES);         // 64 x 68 (tf32)
    float*    Kv0 = (float*)(dsm + SC_BYTES + QS_BYTES); // raw fp32 chunks
    float*    Kv1 = Kv0 + 128 * 68;

    const int bh = blockIdx.y;
    const int b  = bh / H_;
    const int h  = bh % H_;
    const int n0 = blockIdx.x * 64;

    const int tid  = threadIdx.x;
    const int lane = tid & 31;
    const int w    = tid >> 5;          // 0..15
    const int grp  = lane >> 2;
    const int tig  = lane & 3;

    // ---- Phase 1: Q (64x64) as tf32 ----
    {
        int row = tid >> 3, col = (tid & 7) * 8;
        const float* src = g_q + (size_t)(b * 512 + n0 + row) * 768 + h * 64 + col;
        float4 q0 = *(const float4*)src;
        float4 q1 = *(const float4*)(src + 4);
        *(uint4*)&Qs[row * 68 + col]     = make_uint4(f2tf(q0.x), f2tf(q0.y), f2tf(q0.z), f2tf(q0.w));
        *(uint4*)&Qs[row * 68 + col + 4] = make_uint4(f2tf(q1.x), f2tf(q1.y), f2tf(q1.z), f2tf(q1.w));
    }

    // cp.async chunk staging: 128 rows x 64 cols per chunk, 64B per thread
    const int srow = tid >> 2;
    const int scol = (tid & 3) * 16;
    float* bufs[2] = { Kv0, Kv1 };
    const unsigned bufu[2] = { smem_u32(Kv0), smem_u32(Kv1) };
    auto cp_chunk = [&](const float* basep, int mc, int bi) {
        const float* s = basep + (size_t)(b * 512 + mc + srow) * 768 + h * 64 + scol;
        unsigned dst = bufu[bi] + (unsigned)((srow * 68 + scol) * 4);
        cp16(dst, s); cp16(dst + 16, s + 4); cp16(dst + 32, s + 8); cp16(dst + 48, s + 12);
    };

    cp_chunk(g_k, 0, 0); cp_commit();

    // ---- Phase 2: scores over 4 m-chunks ----
    const int qb = (w >> 3) * 32;      // 0 or 32
    const int mb = (w & 7) * 16;       // 0..112
    const unsigned aq0 = smem_u32(Qs) +
        (unsigned)(((qb + (lane & 7) + 8 * ((lane >> 3) & 1)) * 68 + 4 * (lane >> 4)) * 4);
    const unsigned koff =
        (unsigned)(((mb + (lane & 7) + 8 * (lane >> 4)) * 68 + 4 * ((lane >> 3) & 1)) * 4);

    for (int c = 0; c < 4; c++) {
        cp_wait<0>(); __syncthreads();          // chunk c in bufs[c&1]; prior readers done
        if (c < 3) { cp_chunk(g_k, (c + 1) * 128, (c + 1) & 1); cp_commit(); }

        float acc[2][2][4];
#pragma unroll
        for (int i = 0; i < 2; i++)
#pragma unroll
            for (int j = 0; j < 2; j++)
#pragma unroll
                for (int q = 0; q < 4; q++) acc[i][j][q] = 0.f;

        const unsigned kb = bufu[c & 1] + koff;
#pragma unroll
        for (int kc = 0; kc < 64; kc += 8) {
            unsigned af[2][4];
            ldsm4(af[0], aq0 + (unsigned)(kc * 4));
            ldsm4(af[1], aq0 + (unsigned)((16 * 68 + kc) * 4));
            unsigned t[4];
            ldsm4(t, kb + (unsigned)(kc * 4));
#pragma unroll
            for (int q = 0; q < 4; q++) t[q] = cvt_u(t[q]);
            unsigned bf0[2] = { t[0], t[1] };
            unsigned bf1[2] = { t[2], t[3] };
            mma8(acc[0][0], af[0], bf0); mma8(acc[0][1], af[0], bf1);
            mma8(acc[1][0], af[1], bf0); mma8(acc[1][1], af[1], bf1);
        }

        const int mc = c * 128;
#pragma unroll
        for (int qt = 0; qt < 2; qt++) {
#pragma unroll
            for (int p = 0; p < 2; p++) {
                int row = qb + qt * 16 + grp + p * 8;
#pragma unroll
                for (int mt = 0; mt < 2; mt++) {
                    int col = mc + mb + mt * 8 + 2 * tig;
                    size_t em = (size_t)(b * 512 + n0 + row) * 512 + col;
                    float2 e2 = *(const float2*)&g_eb[em];   // mask pre-folded
                    *(float2*)&Sc[row * SC_STRIDE + col] =
                        make_float2(acc[qt][mt][2 * p]     * SCALE_ + e2.x,
                                    acc[qt][mt][2 * p + 1] * SCALE_ + e2.y);
                }
            }
        }
    }

    // prefetch V chunk 0 into buf0 (buf0 last read at c=2; synced at c=3 top)
    cp_chunk(g_v, 0, 0); cp_commit();
    __syncthreads();                            // all Sc scores visible

    // ---- Phase 3: softmax; write attn to gmem; keep tf32 copy in Sc ----
#pragma unroll
    for (int r = 0; r < 4; r++) {
        int row = w * 4 + r;
        float4 v[4];
#pragma unroll
        for (int j = 0; j < 4; j++)
            v[j] = *(float4*)&Sc[row * SC_STRIDE + lane * 4 + j * 128];
        float mx = -1e30f;
#pragma unroll
        for (int j = 0; j < 4; j++)
            mx = fmaxf(mx, fmaxf(fmaxf(v[j].x, v[j].y), fmaxf(v[j].z, v[j].w)));
#pragma unroll
        for (int o = 16; o > 0; o >>= 1)
            mx = fmaxf(mx, __shfl_xor_sync(0xffffffffu, mx, o));
        float sum = 0.f;
#pragma unroll
        for (int j = 0; j < 4; j++) {
            v[j].x = __expf(v[j].x - mx); v[j].y = __expf(v[j].y - mx);
            v[j].z = __expf(v[j].z - mx); v[j].w = __expf(v[j].w - mx);
            sum += v[j].x + v[j].y + v[j].z + v[j].w;
        }
#pragma unroll
        for (int o = 16; o > 0; o >>= 1)
            sum += __shfl_xor_sync(0xffffffffu, sum, o);
        float inv = 1.0f / sum;
        float4* gout = (float4*)&g_attn[((size_t)bh * 512 + n0 + row) * 512];
#pragma unroll
        for (int j = 0; j < 4; j++) {
            float4 nv = make_float4(v[j].x * inv, v[j].y * inv, v[j].z * inv, v[j].w * inv);
            gout[lane + j * 32] = nv;
            *(uint4*)&Sc[row * SC_STRIDE + lane * 4 + j * 128] =
                make_uint4(f2tf(nv.x), f2tf(nv.y), f2tf(nv.z), f2tf(nv.w));
        }
    }
    cp_wait<0>(); __syncthreads();              // V chunk 0 ready; Sc tf32 visible

    // ---- Phase 4: ctx = attn @ v ----
    const int db = (w & 7) * 8;
    float acc2[2][4];
#pragma unroll
    for (int i = 0; i < 2; i++)
#pragma unroll
        for (int q = 0; q < 4; q++) acc2[i][q] = 0.f;

    const unsigned as0 = smem_u32(Sc) +
        (unsigned)(((qb + (lane & 7) + 8 * ((lane >> 3) & 1)) * SC_STRIDE + 4 * (lane >> 4)) * 4);

    for (int c = 0; c < 4; c++) {
        if (c < 3) { cp_chunk(g_v, (c + 1) * 128, (c + 1) & 1); cp_commit(); }
        const float* kvu = bufs[c & 1];
#pragma unroll
        for (int ml = 0; ml < 128; ml += 8) {
            unsigned af[2][4];
            ldsm4(af[0], as0 + (unsigned)((c * 128 + ml) * 4));
            ldsm4(af[1], as0 + (unsigned)((16 * SC_STRIDE + c * 128 + ml) * 4));
            unsigned bf[2];
            bf[0] = f2tf(kvu[(ml + tig) * 68 + db + grp]);
            bf[1] = f2tf(kvu[(ml + tig + 4) * 68 + db + grp]);
            mma8(acc2[0], af[0], bf);
            mma8(acc2[1], af[1], bf);
        }
        if (c < 3) { cp_wait<0>(); __syncthreads(); }
    }

#pragma unroll
    for (int qt = 0; qt < 2; qt++) {
#pragma unroll
        for (int p = 0; p < 2; p++) {
            int row = qb + qt * 16 + grp + p * 8;
            int col = h * 64 + db + 2 * tig;
            *(float2*)&g_cat[(size_t)(b * 512 + n0 + row) * 1536 + col] =
                make_float2(acc2[qt][2 * p], acc2[qt][2 * p + 1]);
        }
    }
}

// ----------------------------------------------------------------------------
// Weight folds (side stream)
// ----------------------------------------------------------------------------
__global__ void __launch_bounds__(256) build_w2_tile(
    const float* __restrict__ Wke, const float* __restrict__ Weo)
{
    __shared__ float Ws[64 * 64];
    const int tid = threadIdx.x;
    const int h   = blockIdx.y;
    const int j0  = blockIdx.x * 128;

#pragma unroll
    for (int i = 0; i < 16; i++)
        Ws[tid + i * 256] = Wke[tid + i * 256];
    __syncthreads();

    const int jl = tid & 127;
    const int c0 = (tid >> 7) * 32;
    float acc[32];
#pragma unroll
    for (int c = 0; c < 32; c++) acc[c] = 0.f;

    for (int e = 0; e < 64; e++) {
        float w = Weo[(size_t)(h * 64 + e) * 768 + j0 + jl];
#pragma unroll
        for (int c = 0; c < 32; c++)
            acc[c] += Ws[(c0 + c) * 64 + e] * w;
    }
#pragma unroll
    for (int c = 0; c < 32; c++)
        g_W2[(size_t)(h * 64 + c0 + c) * 768 + j0 + jl] = acc[c];
}

__global__ void __launch_bounds__(256) build_b2_par(
    const float* __restrict__ bke, const float* __restrict__ Weo,
    const float* __restrict__ beo)
{
    __shared__ float red[8][32];
    const int tid = threadIdx.x;
    const int jl  = tid & 31;
    const int rw  = tid >> 5;
    const int j   = blockIdx.x * 32 + jl;

    float acc = 0.f;
    for (int r = rw; r < 768; r += 8)
        acc += bke[r & 63] * Weo[(size_t)r * 768 + j];
    red[rw][jl] = acc;
    __syncthreads();
    if (rw == 0) {
        float s = beo[j];
#pragma unroll
        for (int i = 0; i < 8; i++) s += red[i][jl];
        g_b2[j] = s;
    }
}

__global__ void __launch_bounds__(256) build_b3_par(
    const float* __restrict__ Wo2, const float* __restrict__ bo)
{
    __shared__ float red[8][32];
    const int tid = threadIdx.x;
    const int jl  = tid & 31;
    const int rw  = tid >> 5;
    const int j   = blockIdx.x * 32 + jl;

    float acc = 0.f;
    for (int r = rw; r < 768; r += 8)
        acc += g_b2[r] * Wo2[(size_t)r * 768 + j];
    red[rw][jl] = acc;
    __syncthreads();
    if (rw == 0) {
        float s = bo[j];
#pragma unroll
        for (int i = 0; i < 8; i++) s += red[i][jl];
        g_b3[j] = s;
    }
}

// ----------------------------------------------------------------------------
// Edge bias (softcap) with mask folded
// ----------------------------------------------------------------------------
__global__ void __launch_bounds__(256) eb_kernel(
    const float* __restrict__ edge, const float* __restrict__ We,
    const float* __restrict__ be, const unsigned char* __restrict__ mask)
{
    int idx  = blockIdx.x * 16 + (threadIdx.x >> 4);
    int l16  = threadIdx.x & 15;
    const float4 e4 = *(const float4*)(edge + (size_t)idx * 64 + l16 * 4);
    const float4 w4 = *(const float4*)(We + l16 * 4);
    float acc = e4.x * w4.x + e4.y * w4.y + e4.z * w4.z + e4.w * w4.w;
#pragma unroll
    for (int o = 8; o > 0; o >>= 1)
        acc += __shfl_xor_sync(0xffffffffu, acc, o);
    if (l16 == 0) {
        float x = (acc + be[0]) * INVSQRT2_;
        float r = CAP_ * tanhf(x * (1.0f / CAP_));
        g_eb[idx] = mask[idx] ? -1e9f : r;
    }
}

// ----------------------------------------------------------------------------
// ae -> g_cat[:, 768:1536]  (cp.async double-buffered edge chunks)
// ----------------------------------------------------------------------------
__global__ void __launch_bounds__(256) ae_kernel(const float* __restrict__ edge)
{
    __shared__ float Es[2][64 * 64];
    __shared__ float Asm[2][12 * 64];

    const int bn = blockIdx.x;
    const int b  = bn >> 9;
    const int n  = bn & 511;

    const int tid = threadIdx.x;
    const int d   = tid & 63;
    const int h0  = tid >> 6;
    const int srow = tid >> 2;
    const int scol = (tid & 3) * 16;

    const float* ebase = edge + (size_t)bn * 512 * 64;
    const unsigned esu[2] = { smem_u32(Es[0]), smem_u32(Es[1]) };

    auto cp_es = [&](int mc, int bi) {
        const float* s = ebase + (size_t)(mc + srow) * 64 + scol;
        unsigned dst = esu[bi] + (unsigned)((srow * 64 + scol) * 4);
        cp16(dst, s); cp16(dst + 16, s + 4); cp16(dst + 32, s + 8); cp16(dst + 48, s + 12);
    };
    auto ld_asm = [&](int mc, int bi) {
#pragma unroll
        for (int i = 0; i < 3; i++) {
            int lin = tid + i * 256;
            int hh = lin >> 6, mm = lin & 63;
            Asm[bi][lin] = g_attn[(((size_t)(b * H_ + hh)) * 512 + n) * 512 + mc + mm];
        }
    };

    cp_es(0, 0); cp_commit();
    ld_asm(0, 0);

    float acc0 = 0.f, acc1 = 0.f, acc2 = 0.f;

    for (int c = 0; c < 8; c++) {
        cp_wait<0>(); __syncthreads();
        if (c < 7) {
            cp_es((c + 1) * 64, (c + 1) & 1); cp_commit();
            ld_asm((c + 1) * 64, (c + 1) & 1);
        }
        const float* E = Es[c & 1];
        const float* A = Asm[c & 1];
#pragma unroll 4
        for (int m = 0; m < 64; m += 4) {
            float4 a0 = *(const float4*)&A[(h0    ) * 64 + m];
            float4 a1 = *(const float4*)&A[(h0 + 4) * 64 + m];
            float4 a2 = *(const float4*)&A[(h0 + 8) * 64 + m];
            float e0 = E[(m + 0) * 64 + d];
            float e1 = E[(m + 1) * 64 + d];
            float e2 = E[(m + 2) * 64 + d];
            float e3 = E[(m + 3) * 64 + d];
            acc0 += a0.x * e0 + a0.y * e1 + a0.z * e2 + a0.w * e3;
            acc1 += a1.x * e0 + a1.y * e1 + a1.z * e2 + a1.w * e3;
            acc2 += a2.x * e0 + a2.y * e1 + a2.z * e2 + a2.w * e3;
        }
    }

    float* ar = g_cat + (size_t)bn * 1536 + 768;
    ar[(h0    ) * 64 + d] = acc0;
    ar[(h0 + 4) * 64 + d] = acc1;
    ar[(h0 + 8) * 64 + d] = acc2;
}

// ----------------------------------------------------------------------------
// Launch. attn_fused is API launch index 3 (ncu capture target this round).
// ----------------------------------------------------------------------------
extern "C" void kernel_launch(void* const* d_in, const int* in_sizes, int n_in,
                              void* d_out, int out_size)
{
    const float* Q    = (const float*)d_in[0];
    const float* Kin  = (const float*)d_in[1];
    const float* V    = (const float*)d_in[2];
    const unsigned char* mask = (const unsigned char*)d_in[3];
    const float* edge = (const float*)d_in[4];
    const float* Wq   = (const float*)d_in[5];
    const float* bq   = (const float*)d_in[6];
    const float* Wk   = (const float*)d_in[7];
    const float* bk   = (const float*)d_in[8];
    const float* Wv   = (const float*)d_in[9];
    const float* bv   = (const float*)d_in[10];
    const float* Wke  = (const float*)d_in[11];
    const float* bke  = (const float*)d_in[12];
    const float* We   = (const float*)d_in[13];
    const float* be   = (const float*)d_in[14];
    const float* Weo  = (const float*)d_in[15];
    const float* beo  = (const float*)d_in[16];
    const float* Wo   = (const float*)d_in[17];
    const float* bo   = (const float*)d_in[18];
    float* out = (float*)d_out;

    void *pq, *pk, *pv, *pcat, *pW2, *pW3, *pb3;
    cudaGetSymbolAddress(&pq,   g_q);
    cudaGetSymbolAddress(&pk,   g_k);
    cudaGetSymbolAddress(&pv,   g_v);
    cudaGetSymbolAddress(&pcat, g_cat);
    cudaGetSymbolAddress(&pW2,  g_W2);
    cudaGetSymbolAddress(&pW3,  g_W3);
    cudaGetSymbolAddress(&pb3,  g_b3);

    static cudaStream_t s1 = nullptr;
    static cudaEvent_t evA = nullptr, evB = nullptr, evC = nullptr, evD = nullptr, evE = nullptr;
    if (!s1) {
        cudaStreamCreateWithFlags(&s1, cudaStreamNonBlocking);
        cudaEventCreateWithFlags(&evA, cudaEventDisableTiming);
        cudaEventCreateWithFlags(&evB, cudaEventDisableTiming);
        cudaEventCreateWithFlags(&evC, cudaEventDisableTiming);
        cudaEventCreateWithFlags(&evD, cudaEventDisableTiming);
        cudaEventCreateWithFlags(&evE, cudaEventDisableTiming);
        cudaFuncSetAttribute(attn_fused, cudaFuncAttributeMaxDynamicSharedMemorySize, ATTN_SMEM);
        cudaFuncSetAttribute(gemm_nn<true>,  cudaFuncAttributeMaxDynamicSharedMemorySize, GNN_SMEM);
        cudaFuncSetAttribute(gemm_nn<false>, cudaFuncAttributeMaxDynamicSharedMemorySize, GNN_SMEM);
    }

    cudaEventRecord(evA, 0);
    cudaStreamWaitEvent(s1, evA, 0);

    eb_kernel<<<(B_ * L_ * L_) / 16, 256, 0, s1>>>(edge, We, be, mask);  // 0

    // QKV projections on stream 0
    {
        GArgs a;
        a.K = 768; a.K1 = 768; a.lda = 768;
        a.g[0] = GArg{Q,   Wq, Wq, bq, (float*)pq};
        a.g[1] = GArg{Kin, Wk, Wk, bk, (float*)pk};
        a.g[2] = GArg{V,   Wv, Wv, bv, (float*)pv};
        gemm_nn<true><<<dim3(6, 16, 3), 256, GNN_SMEM>>>(a);             // 1
    }
    cudaEventRecord(evB, s1);

    build_w2_tile<<<dim3(6, 12), 256, 0, s1>>>(Wke, Weo);                // 2

    // Fused attention — API launch index 3 (ncu capture target)
    cudaStreamWaitEvent(0, evB, 0);
    attn_fused<<<dim3(8, B_ * H_), 512, ATTN_SMEM>>>();                  // 3
    cudaEventRecord(evC, 0);

    build_b2_par<<<24, 256, 0, s1>>>(bke, Weo, beo);                     // 4
    build_b3_par<<<24, 256, 0, s1>>>(Wo + 768 * 768, bo);                // 5
    {
        GArgs a;
        a.K = 768; a.K1 = 768; a.lda = 768;
        a.g[0] = GArg{(const float*)pW2, Wo + 768 * 768, Wo, nullptr, (float*)pW3};
        a.g[1] = a.g[0]; a.g[2] = a.g[0];
        gemm_nn<false><<<dim3(6, 6, 1), 256, GNN_SMEM, s1>>>(a);         // 6: W3 = W2@Wo2
    }
    cudaEventRecord(evE, s1);

    // ae on side stream (needs g_attn)
    cudaStreamWaitEvent(s1, evC, 0);
    ae_kernel<<<B_ * L_, 256, 0, s1>>>(edge);                            // 7
    cudaEventRecord(evD, s1);

    // final1: out = ctx @ Wo1 + b3  (overlaps ae)
    cudaStreamWaitEvent(0, evE, 0);
    {
        GArgs a;
        a.K = 768; a.K1 = 768; a.lda = 1536;
        a.g[0] = GArg{(const float*)pcat, Wo, Wo, (const float*)pb3, out};
        a.g[1] = a.g[0]; a.g[2] = a.g[0];
        gemm_nn64<true, false><<<dim3(6, 32, 1), 128>>>(a);              // 8
    }

    // final2: out += ae @ W3
    cudaStreamWaitEvent(0, evD, 0);
    {
        GArgs a;
        a.K = 768; a.K1 = 768; a.lda = 1536;
        a.g[0] = GArg{(const float*)pcat + 768, (const float*)pW3, (const float*)pW3, nullptr, out};
        a.g[1] = a.g[0]; a.g[2] = a.g[0];
        gemm_nn64<false, true><<<dim3(6, 32, 1), 128>>>(a);              // 9
    }
}

// round 12
// speedup vs baseline: 1.1239x; 1.0452x over previous
#include <cuda_runtime.h>
#include <math.h>
#include <stdint.h>

constexpr int B_  = 4;
constexpr int L_  = 512;
constexpr int D_  = 768;
constexpr int H_  = 12;
constexpr int M_  = B_ * L_;
constexpr float SCALE_    = 0.08838834764831845f;
constexpr float INVSQRT2_ = 0.70710678118654752f;
constexpr float CAP_      = 5.0f;

// Scratch
__device__ float g_q   [M_ * D_];
__device__ float g_k   [M_ * D_];
__device__ float g_v   [M_ * D_];
__device__ float g_eb  [B_ * L_ * L_];                // eb with mask folded in
__device__ float g_attn[(size_t)B_ * H_ * L_ * L_];
__device__ float g_cat [M_ * 2 * D_];
__device__ float g_W2  [D_ * D_];
__device__ float g_W3  [D_ * D_];
__device__ float g_b2  [D_];
__device__ float g_b3  [D_];

// ----------------------------------------------------------------------------
// helpers
// ----------------------------------------------------------------------------
__device__ __forceinline__ unsigned f2tf(float x) {
    unsigned u;
    asm("cvt.rna.tf32.f32 %0, %1;" : "=r"(u) : "f"(x));
    return u;
}
__device__ __forceinline__ unsigned cvt_u(unsigned x) {
    return f2tf(__uint_as_float(x));
}
__device__ __forceinline__ void mma8(float* c, const unsigned* a, const unsigned* b) {
    asm volatile(
        "mma.sync.aligned.m16n8k8.row.col.f32.tf32.tf32.f32 "
        "{%0,%1,%2,%3}, {%4,%5,%6,%7}, {%8,%9}, {%0,%1,%2,%3};"
        : "+f"(c[0]), "+f"(c[1]), "+f"(c[2]), "+f"(c[3])
        : "r"(a[0]), "r"(a[1]), "r"(a[2]), "r"(a[3]), "r"(b[0]), "r"(b[1]));
}
__device__ __forceinline__ unsigned smem_u32(const void* p) {
    return (unsigned)__cvta_generic_to_shared(p);
}
__device__ __forceinline__ void ldsm4(unsigned* r, unsigned a) {
    asm volatile("ldmatrix.sync.aligned.m8n8.x4.shared.b16 {%0,%1,%2,%3}, [%4];"
        : "=r"(r[0]), "=r"(r[1]), "=r"(r[2]), "=r"(r[3]) : "r"(a));
}
__device__ __forceinline__ void cp16(unsigned dst, const void* src) {
    asm volatile("cp.async.cg.shared.global [%0], [%1], 16;" :: "r"(dst), "l"(src));
}
__device__ __forceinline__ void cp_commit() {
    asm volatile("cp.async.commit_group;");
}
template<int N>
__device__ __forceinline__ void cp_wait() {
    asm volatile("cp.async.wait_group %0;" :: "n"(N));
}

struct GArg  { const float* A; const float* Bm; const float* B2; const float* bias; float* C; };
struct GArgs { GArg g[3]; int K; int K1; int lda; };

// ----------------------------------------------------------------------------
// NN tf32 GEMM: BM=128 BN=128 BK=16, 256 threads, cp.async 3-stage
// (measured 61us on QKV). Dynamic smem 56832 B. Requires (K/16)%3==0.
// ----------------------------------------------------------------------------
constexpr int GNN_SMEM = (3 * 128 * 20 + 3 * 16 * 136) * 4;   // 56832

template<bool BIAS>
__global__ void __launch_bounds__(256, 2) gemm_nn(GArgs args)
{
    extern __shared__ unsigned dyn[];
    unsigned* Asb[3] = { dyn, dyn + 2560, dyn + 5120 };
    unsigned* Bsb[3] = { dyn + 7680, dyn + 7680 + 2176, dyn + 7680 + 4352 };

    const GArg ga = args.g[blockIdx.z];
    const int K  = args.K;
    const int K1 = args.K1;
    const int T  = K >> 4;

    const int tid  = threadIdx.x;
    const int lane = tid & 31;
    const int wid  = tid >> 5;
    const int grp  = lane >> 2;
    const int tig  = lane & 3;
    const int wm0  = (wid >> 1) * 32;
    const int wn0  = (wid & 1) * 64;
    const int m0   = blockIdx.y * 128;
    const int n0   = blockIdx.x * 128;

    float acc[2][8][4];
#pragma unroll
    for (int i = 0; i < 2; i++)
#pragma unroll
        for (int j = 0; j < 8; j++)
#pragma unroll
            for (int q = 0; q < 4; q++) acc[i][j][q] = 0.f;

    const int a_r = tid >> 1, a_c = (tid & 1) * 8;
    const int b_r = tid >> 4, b_c = (tid & 15) * 8;
    const float* Agbase = ga.A + (size_t)(m0 + a_r) * K + a_c;
    const unsigned a_off = (unsigned)((a_r * 20 + a_c) * 4);
    const unsigned b_off = (unsigned)((b_r * 136 + b_c) * 4);

    const int lrow = wm0 + (lane & 7) + 8 * ((lane >> 3) & 1);
    const int lcol = 4 * (lane >> 4);
    unsigned abf[3];
#pragma unroll
    for (int i = 0; i < 3; i++)
        abf[i] = smem_u32(Asb[i]) + (unsigned)((lrow * 20 + lcol) * 4);
    unsigned asd[3], bsd[3];
#pragma unroll
    for (int i = 0; i < 3; i++) { asd[i] = smem_u32(Asb[i]); bsd[i] = smem_u32(Bsb[i]); }

    auto cp_tile = [&](int it, int buf) {
        const int kk = it * 16;
        const float* as = Agbase + kk;
        cp16(asd[buf] + a_off, as);
        cp16(asd[buf] + a_off + 16, as + 4);
        const int krow = kk + b_r;
        const float* bsrc = (krow < K1 ? ga.Bm + (size_t)krow * 768
                                       : ga.B2 + (size_t)(krow - K1) * 768) + n0 + b_c;
        cp16(bsd[buf] + b_off, bsrc);
        cp16(bsd[buf] + b_off + 16, bsrc + 4);
    };

    auto mma_tile = [&](int buf) {
        const unsigned abase = abf[buf];
        const unsigned* Bp = Bsb[buf];
#pragma unroll
        for (int kc = 0; kc < 16; kc += 8) {
            unsigned af[2][4];
            ldsm4(af[0], abase + (unsigned)(kc * 4));
            ldsm4(af[1], abase + (unsigned)((16 * 20 + kc) * 4));
#pragma unroll
            for (int i = 0; i < 2; i++)
#pragma unroll
                for (int q = 0; q < 4; q++) af[i][q] = cvt_u(af[i][q]);
            unsigned bf[8][2];
#pragma unroll
            for (int j = 0; j < 8; j++) {
                bf[j][0] = cvt_u(Bp[(kc + tig) * 136 + wn0 + j * 8 + grp]);
                bf[j][1] = cvt_u(Bp[(kc + tig + 4) * 136 + wn0 + j * 8 + grp]);
            }
#pragma unroll
            for (int i = 0; i < 2; i++)
#pragma unroll
                for (int j = 0; j < 8; j++) mma8(acc[i][j], af[i], bf[j]);
        }
    };

    cp_tile(0, 0); cp_commit();
    cp_tile(1, 1); cp_commit();

    for (int it = 0; it < T; it += 3) {
        cp_wait<1>(); __syncthreads();
        if (it + 2 < T) cp_tile(it + 2, 2);
        cp_commit();
        mma_tile(0);

        cp_wait<1>(); __syncthreads();
        if (it + 3 < T) cp_tile(it + 3, 0);
        cp_commit();
        mma_tile(1);

        cp_wait<1>(); __syncthreads();
        if (it + 4 < T) cp_tile(it + 4, 1);
        cp_commit();
        mma_tile(2);
    }

#pragma unroll
    for (int i = 0; i < 2; i++) {
        int r0 = m0 + wm0 + i * 16 + grp;
#pragma unroll
        for (int j = 0; j < 8; j++) {
            int c = n0 + wn0 + j * 8 + 2 * tig;
            float b0 = 0.f, b1 = 0.f;
            if (BIAS) { b0 = ga.bias[c]; b1 = ga.bias[c + 1]; }
            *(float2*)&ga.C[(size_t)r0 * 768 + c] =
                make_float2(acc[i][j][0] + b0, acc[i][j][1] + b1);
            *(float2*)&ga.C[(size_t)(r0 + 8) * 768 + c] =
                make_float2(acc[i][j][2] + b0, acc[i][j][3] + b1);
        }
    }
}

// ----------------------------------------------------------------------------
// NN tf32 GEMM: BM=64 BN=128, 128 thr, cp.async 3-stage (unchanged).
// ----------------------------------------------------------------------------
template<bool BIAS, bool ACC>
__global__ void __launch_bounds__(128, 3) gemm_nn64(GArgs args)
{
    const GArg ga = args.g[blockIdx.z];
    const int K   = args.K;
    const int K1  = args.K1;
    const int lda = args.lda;
    const int T   = K >> 4;

    __shared__ alignas(16) unsigned As[3][64 * 20];
    __shared__ alignas(16) unsigned Bs[3][16 * 136];

    const int tid  = threadIdx.x;
    const int lane = tid & 31;
    const int wid  = tid >> 5;
    const int grp  = lane >> 2;
    const int tig  = lane & 3;
    const int wm0  = (wid >> 1) * 32;
    const int wn0  = (wid & 1) * 64;
    const int m0   = blockIdx.y * 64;
    const int n0   = blockIdx.x * 128;

    float acc[2][8][4];
#pragma unroll
    for (int i = 0; i < 2; i++)
#pragma unroll
        for (int j = 0; j < 8; j++)
#pragma unroll
            for (int q = 0; q < 4; q++) acc[i][j][q] = 0.f;

    const int a_r = tid >> 1;
    const int a_c = (tid & 1) * 8;
    const float* Agbase = ga.A + (size_t)(m0 + a_r) * lda + a_c;
    const unsigned a_off = (unsigned)((a_r * 20 + a_c) * 4);
    const int b_r = tid >> 3;
    const int b_c = (tid & 7) * 16;
    const unsigned b_off = (unsigned)((b_r * 136 + b_c) * 4);

    const int lrow = wm0 + (lane & 7) + 8 * ((lane >> 3) & 1);
    const int lcol = 4 * (lane >> 4);
    const unsigned ab0 = smem_u32(As[0]) + (unsigned)((lrow * 20 + lcol) * 4);
    const unsigned ab1 = smem_u32(As[1]) + (unsigned)((lrow * 20 + lcol) * 4);
    const unsigned ab2 = smem_u32(As[2]) + (unsigned)((lrow * 20 + lcol) * 4);

    auto cp_tile = [&](int it, unsigned adst, unsigned bdst) {
        const int kk = it * 16;
        const float* as = Agbase + kk;
#pragma unroll
        for (int c = 0; c < 2; c++) cp16(adst + a_off + c * 16, as + c * 4);
        const int krow = kk + b_r;
        const float* bsrc = (krow < K1 ? ga.Bm + (size_t)krow * 768
                                       : ga.B2 + (size_t)(krow - K1) * 768) + n0 + b_c;
#pragma unroll
        for (int c = 0; c < 4; c++) cp16(bdst + b_off + c * 16, bsrc + c * 4);
    };

    auto mma_tile = [&](unsigned abase, const unsigned* Bsb) {
#pragma unroll
        for (int kc = 0; kc < 16; kc += 8) {
            unsigned af[2][4];
#pragma unroll
            for (int i = 0; i < 2; i++) {
                ldsm4(af[i], abase + (unsigned)((i * 16 * 20 + kc) * 4));
#pragma unroll
                for (int q = 0; q < 4; q++) af[i][q] = cvt_u(af[i][q]);
            }
            unsigned bf[8][2];
#pragma unroll
            for (int j = 0; j < 8; j++) {
                bf[j][0] = cvt_u(Bsb[(kc + tig) * 136 + wn0 + j * 8 + grp]);
                bf[j][1] = cvt_u(Bsb[(kc + tig + 4) * 136 + wn0 + j * 8 + grp]);
            }
#pragma unroll
            for (int i = 0; i < 2; i++)
#pragma unroll
                for (int j = 0; j < 8; j++) mma8(acc[i][j], af[i], bf[j]);
        }
    };

    const unsigned asd0 = smem_u32(As[0]), asd1 = smem_u32(As[1]), asd2 = smem_u32(As[2]);
    const unsigned bsd0 = smem_u32(Bs[0]), bsd1 = smem_u32(Bs[1]), bsd2 = smem_u32(Bs[2]);

    cp_tile(0, asd0, bsd0); cp_commit();
    cp_tile(1, asd1, bsd1); cp_commit();

    for (int it = 0; it < T; it += 3) {
        cp_wait<1>(); __syncthreads();
        if (it + 2 < T) cp_tile(it + 2, asd2, bsd2);
        cp_commit();
        mma_tile(ab0, Bs[0]);

        cp_wait<1>(); __syncthreads();
        if (it + 3 < T) cp_tile(it + 3, asd0, bsd0);
        cp_commit();
        mma_tile(ab1, Bs[1]);

        cp_wait<1>(); __syncthreads();
        if (it + 4 < T) cp_tile(it + 4, asd1, bsd1);
        cp_commit();
        mma_tile(ab2, Bs[2]);
    }

#pragma unroll
    for (int i = 0; i < 2; i++) {
        int r0 = m0 + wm0 + i * 16 + grp;
#pragma unroll
        for (int j = 0; j < 8; j++) {
            int c = n0 + wn0 + j * 8 + 2 * tig;
            float b0 = 0.f, b1 = 0.f;
            if (BIAS) { b0 = ga.bias[c]; b1 = ga.bias[c + 1]; }
            float2 o0 = make_float2(acc[i][j][0] + b0, acc[i][j][1] + b1);
            float2 o1 = make_float2(acc[i][j][2] + b0, acc[i][j][3] + b1);
            float2* p0 = (float2*)&ga.C[(size_t)r0 * 768 + c];
            float2* p1 = (float2*)&ga.C[(size_t)(r0 + 8) * 768 + c];
            if (ACC) {
                float2 e0 = *p0, e1 = *p1;
                o0.x += e0.x; o0.y += e0.y; o1.x += e1.x; o1.y += e1.y;
            }
            *p0 = o0; *p1 = o1;
        }
    }
}

// ----------------------------------------------------------------------------
// Fused attention (64 q-rows, 512 threads, cp.async) — unchanged from R11.
// ----------------------------------------------------------------------------
constexpr int SC_STRIDE = 516;
constexpr int SC_BYTES  = 64 * SC_STRIDE * 4;
constexpr int QS_BYTES  = 64 * 68 * 4;
constexpr int KV_BYTES  = 128 * 68 * 4;
constexpr int ATTN_SMEM = SC_BYTES + QS_BYTES + 2 * KV_BYTES;  // 219136

__global__ void __launch_bounds__(512, 1) attn_fused()
{
    extern __shared__ char dsm[];
    float*    Sc  = (float*)dsm;
    unsigned* Qs  = (unsigned*)(dsm + SC_BYTES);
    float*    Kv0 = (float*)(dsm + SC_BYTES + QS_BYTES);
    float*    Kv1 = Kv0 + 128 * 68;

    const int bh = blockIdx.y;
    const int b  = bh / H_;
    const int h  = bh % H_;
    const int n0 = blockIdx.x * 64;

    const int tid  = threadIdx.x;
    const int lane = tid & 31;
    const int w    = tid >> 5;
    const int grp  = lane >> 2;
    const int tig  = lane & 3;

    {
        int row = tid >> 3, col = (tid & 7) * 8;
        const float* src = g_q + (size_t)(b * 512 + n0 + row) * 768 + h * 64 + col;
        float4 q0 = *(const float4*)src;
        float4 q1 = *(const float4*)(src + 4);
        *(uint4*)&Qs[row * 68 + col]     = make_uint4(f2tf(q0.x), f2tf(q0.y), f2tf(q0.z), f2tf(q0.w));
        *(uint4*)&Qs[row * 68 + col + 4] = make_uint4(f2tf(q1.x), f2tf(q1.y), f2tf(q1.z), f2tf(q1.w));
    }

    const int srow = tid >> 2;
    const int scol = (tid & 3) * 16;
    float* bufs[2] = { Kv0, Kv1 };
    const unsigned bufu[2] = { smem_u32(Kv0), smem_u32(Kv1) };
    auto cp_chunk = [&](const float* basep, int mc, int bi) {
        const float* s = basep + (size_t)(b * 512 + mc + srow) * 768 + h * 64 + scol;
        unsigned dst = bufu[bi] + (unsigned)((srow * 68 + scol) * 4);
        cp16(dst, s); cp16(dst + 16, s + 4); cp16(dst + 32, s + 8); cp16(dst + 48, s + 12);
    };

    cp_chunk(g_k, 0, 0); cp_commit();

    const int qb = (w >> 3) * 32;
    const int mb = (w & 7) * 16;
    const unsigned aq0 = smem_u32(Qs) +
        (unsigned)(((qb + (lane & 7) + 8 * ((lane >> 3) & 1)) * 68 + 4 * (lane >> 4)) * 4);
    const unsigned koff =
        (unsigned)(((mb + (lane & 7) + 8 * (lane >> 4)) * 68 + 4 * ((lane >> 3) & 1)) * 4);

    for (int c = 0; c < 4; c++) {
        cp_wait<0>(); __syncthreads();
        if (c < 3) { cp_chunk(g_k, (c + 1) * 128, (c + 1) & 1); cp_commit(); }

        float acc[2][2][4];
#pragma unroll
        for (int i = 0; i < 2; i++)
#pragma unroll
            for (int j = 0; j < 2; j++)
#pragma unroll
                for (int q = 0; q < 4; q++) acc[i][j][q] = 0.f;

        const unsigned kb = bufu[c & 1] + koff;
#pragma unroll
        for (int kc = 0; kc < 64; kc += 8) {
            unsigned af[2][4];
            ldsm4(af[0], aq0 + (unsigned)(kc * 4));
            ldsm4(af[1], aq0 + (unsigned)((16 * 68 + kc) * 4));
            unsigned t[4];
            ldsm4(t, kb + (unsigned)(kc * 4));
#pragma unroll
            for (int q = 0; q < 4; q++) t[q] = cvt_u(t[q]);
            unsigned bf0[2] = { t[0], t[1] };
            unsigned bf1[2] = { t[2], t[3] };
            mma8(acc[0][0], af[0], bf0); mma8(acc[0][1], af[0], bf1);
            mma8(acc[1][0], af[1], bf0); mma8(acc[1][1], af[1], bf1);
        }

        const int mc = c * 128;
#pragma unroll
        for (int qt = 0; qt < 2; qt++) {
#pragma unroll
            for (int p = 0; p < 2; p++) {
                int row = qb + qt * 16 + grp + p * 8;
#pragma unroll
                for (int mt = 0; mt < 2; mt++) {
                    int col = mc + mb + mt * 8 + 2 * tig;
                    size_t em = (size_t)(b * 512 + n0 + row) * 512 + col;
                    float2 e2 = *(const float2*)&g_eb[em];
                    *(float2*)&Sc[row * SC_STRIDE + col] =
                        make_float2(acc[qt][mt][2 * p]     * SCALE_ + e2.x,
                                    acc[qt][mt][2 * p + 1] * SCALE_ + e2.y);
                }
            }
        }
    }

    cp_chunk(g_v, 0, 0); cp_commit();
    __syncthreads();

#pragma unroll
    for (int r = 0; r < 4; r++) {
        int row = w * 4 + r;
        float4 v[4];
#pragma unroll
        for (int j = 0; j < 4; j++)
            v[j] = *(float4*)&Sc[row * SC_STRIDE + lane * 4 + j * 128];
        float mx = -1e30f;
#pragma unroll
        for (int j = 0; j < 4; j++)
            mx = fmaxf(mx, fmaxf(fmaxf(v[j].x, v[j].y), fmaxf(v[j].z, v[j].w)));
#pragma unroll
        for (int o = 16; o > 0; o >>= 1)
            mx = fmaxf(mx, __shfl_xor_sync(0xffffffffu, mx, o));
        float sum = 0.f;
#pragma unroll
        for (int j = 0; j < 4; j++) {
            v[j].x = __expf(v[j].x - mx); v[j].y = __expf(v[j].y - mx);
            v[j].z = __expf(v[j].z - mx); v[j].w = __expf(v[j].w - mx);
            sum += v[j].x + v[j].y + v[j].z + v[j].w;
        }
#pragma unroll
        for (int o = 16; o > 0; o >>= 1)
            sum += __shfl_xor_sync(0xffffffffu, sum, o);
        float inv = 1.0f / sum;
        float4* gout = (float4*)&g_attn[((size_t)bh * 512 + n0 + row) * 512];
#pragma unroll
        for (int j = 0; j < 4; j++) {
            float4 nv = make_float4(v[j].x * inv, v[j].y * inv, v[j].z * inv, v[j].w * inv);
            gout[lane + j * 32] = nv;
            *(uint4*)&Sc[row * SC_STRIDE + lane * 4 + j * 128] =
                make_uint4(f2tf(nv.x), f2tf(nv.y), f2tf(nv.z), f2tf(nv.w));
        }
    }
    cp_wait<0>(); __syncthreads();

    const int db = (w & 7) * 8;
    float acc2[2][4];
#pragma unroll
    for (int i = 0; i < 2; i++)
#pragma unroll
        for (int q = 0; q < 4; q++) acc2[i][q] = 0.f;

    const unsigned as0 = smem_u32(Sc) +
        (unsigned)(((qb + (lane & 7) + 8 * ((lane >> 3) & 1)) * SC_STRIDE + 4 * (lane >> 4)) * 4);

    for (int c = 0; c < 4; c++) {
        if (c < 3) { cp_chunk(g_v, (c + 1) * 128, (c + 1) & 1); cp_commit(); }
        const float* kvu = bufs[c & 1];
#pragma unroll
        for (int ml = 0; ml < 128; ml += 8) {
            unsigned af[2][4];
            ldsm4(af[0], as0 + (unsigned)((c * 128 + ml) * 4));
            ldsm4(af[1], as0 + (unsigned)((16 * SC_STRIDE + c * 128 + ml) * 4));
            unsigned bf[2];
            bf[0] = f2tf(kvu[(ml + tig) * 68 + db + grp]);
            bf[1] = f2tf(kvu[(ml + tig + 4) * 68 + db + grp]);
            mma8(acc2[0], af[0], bf);
            mma8(acc2[1], af[1], bf);
        }
        if (c < 3) { cp_wait<0>(); __syncthreads(); }
    }

#pragma unroll
    for (int qt = 0; qt < 2; qt++) {
#pragma unroll
        for (int p = 0; p < 2; p++) {
            int row = qb + qt * 16 + grp + p * 8;
            int col = h * 64 + db + 2 * tig;
            *(float2*)&g_cat[(size_t)(b * 512 + n0 + row) * 1536 + col] =
                make_float2(acc2[qt][2 * p], acc2[qt][2 * p + 1]);
        }
    }
}

// ----------------------------------------------------------------------------
// ae via tensor cores: per (b,n): C(16x64) = attn[b,:,n,:](16x512 pad) @
// edge[b,n,:,:](512x64). 128 threads (4 warps, N split 16/warp, K streamed
// in 8 x 64-row cp.async double-buffered chunks). Rows 12..15 zero-padded.
// ----------------------------------------------------------------------------
__global__ void __launch_bounds__(128) ae_mma(const float* __restrict__ edge)
{
    __shared__ alignas(16) float Eg[2][64 * 72];   // edge chunk [m][d], pad 72
    __shared__ alignas(16) float Am[2][16 * 68];   // attn chunk [h][k], pad 68

    const int bn = blockIdx.x;
    const int b  = bn >> 9;
    const int n  = bn & 511;

    const int tid  = threadIdx.x;
    const int lane = tid & 31;
    const int w    = tid >> 5;          // 0..3
    const int grp  = lane >> 2;
    const int tig  = lane & 3;
    const int wn   = w * 16;

    // zero pad rows 12..15 of both attn buffers (written once, never touched)
    for (int i = tid; i < 2 * 4 * 68; i += 128) {
        int bi = i / (4 * 68), r = i % (4 * 68);
        Am[bi][12 * 68 + r] = 0.f;
    }

    const unsigned egu[2] = { smem_u32(Eg[0]), smem_u32(Eg[1]) };
    const unsigned amu[2] = { smem_u32(Am[0]), smem_u32(Am[1]) };
    const float* ebase = edge + (size_t)bn * 512 * 64;

    auto cp_edge = [&](int mc, int bi) {
        int row = tid >> 1, ch = (tid & 1) * 32;
        const float* s = ebase + (size_t)(mc + row) * 64 + ch;
        unsigned dst = egu[bi] + (unsigned)((row * 72 + ch) * 4);
#pragma unroll
        for (int c = 0; c < 8; c++) cp16(dst + c * 16, s + c * 4);
    };
    auto cp_attn = [&](int mc, int bi) {
        if (tid < 96) {
            int hh = tid >> 3, seg = (tid & 7) * 8;
            const float* s = g_attn + (((size_t)(b * H_ + hh)) * 512 + n) * 512 + mc + seg;
            unsigned dst = amu[bi] + (unsigned)((hh * 68 + seg) * 4);
            cp16(dst, s); cp16(dst + 16, s + 4);
        }
    };

    cp_attn(0, 0); cp_edge(0, 0); cp_commit();
    __syncthreads();   // zero-fill visible

    const int lrow = (lane & 7) + 8 * ((lane >> 3) & 1);
    const int lcol = 4 * (lane >> 4);

    float acc[2][4];
#pragma unroll
    for (int j = 0; j < 2; j++)
#pragma unroll
        for (int q = 0; q < 4; q++) acc[j][q] = 0.f;

    for (int c = 0; c < 8; c++) {
        cp_wait<0>(); __syncthreads();
        if (c < 7) {
            cp_attn((c + 1) * 64, (c + 1) & 1);
            cp_edge((c + 1) * 64, (c + 1) & 1);
            cp_commit();
        }
        const unsigned ab = amu[c & 1] + (unsigned)((lrow * 68 + lcol) * 4);
        const float* E = Eg[c & 1];
#pragma unroll
        for (int kc = 0; kc < 64; kc += 8) {
            unsigned af[4];
            ldsm4(af, ab + (unsigned)(kc * 4));
#pragma unroll
            for (int q = 0; q < 4; q++) af[q] = cvt_u(af[q]);
#pragma unroll
            for (int j = 0; j < 2; j++) {
                unsigned bf[2];
                bf[0] = f2tf(E[(kc + tig) * 72 + wn + j * 8 + grp]);
                bf[1] = f2tf(E[(kc + tig + 4) * 72 + wn + j * 8 + grp]);
                mma8(acc[j], af, bf);
            }
        }
    }

    float* ar = g_cat + (size_t)bn * 1536 + 768;
#pragma unroll
    for (int p = 0; p < 2; p++) {
        int row = grp + p * 8;
        if (row < 12) {
#pragma unroll
            for (int j = 0; j < 2; j++) {
                int col = wn + j * 8 + 2 * tig;
                *(float2*)&ar[row * 64 + col] = make_float2(acc[j][2 * p], acc[j][2 * p + 1]);
            }
        }
    }
}

// ----------------------------------------------------------------------------
// Weight folds
// ----------------------------------------------------------------------------
__global__ void __launch_bounds__(256) build_w2_tile(
    const float* __restrict__ Wke, const float* __restrict__ Weo)
{
    __shared__ float Ws[64 * 64];
    const int tid = threadIdx.x;
    const int h   = blockIdx.y;
    const int j0  = blockIdx.x * 128;

#pragma unroll
    for (int i = 0; i < 16; i++)
        Ws[tid + i * 256] = Wke[tid + i * 256];
    __syncthreads();

    const int jl = tid & 127;
    const int c0 = (tid >> 7) * 32;
    float acc[32];
#pragma unroll
    for (int c = 0; c < 32; c++) acc[c] = 0.f;

    for (int e = 0; e < 64; e++) {
        float w = Weo[(size_t)(h * 64 + e) * 768 + j0 + jl];
#pragma unroll
        for (int c = 0; c < 32; c++)
            acc[c] += Ws[(c0 + c) * 64 + e] * w;
    }
#pragma unroll
    for (int c = 0; c < 32; c++)
        g_W2[(size_t)(h * 64 + c0 + c) * 768 + j0 + jl] = acc[c];
}

__global__ void __launch_bounds__(256) build_b2_par(
    const float* __restrict__ bke, const float* __restrict__ Weo,
    const float* __restrict__ beo)
{
    __shared__ float red[8][32];
    const int tid = threadIdx.x;
    const int jl  = tid & 31;
    const int rw  = tid >> 5;
    const int j   = blockIdx.x * 32 + jl;

    float acc = 0.f;
    for (int r = rw; r < 768; r += 8)
        acc += bke[r & 63] * Weo[(size_t)r * 768 + j];
    red[rw][jl] = acc;
    __syncthreads();
    if (rw == 0) {
        float s = beo[j];
#pragma unroll
        for (int i = 0; i < 8; i++) s += red[i][jl];
        g_b2[j] = s;
    }
}

__global__ void __launch_bounds__(256) build_b3_par(
    const float* __restrict__ Wo2, const float* __restrict__ bo)
{
    __shared__ float red[8][32];
    const int tid = threadIdx.x;
    const int jl  = tid & 31;
    const int rw  = tid >> 5;
    const int j   = blockIdx.x * 32 + jl;

    float acc = 0.f;
    for (int r = rw; r < 768; r += 8)
        acc += g_b2[r] * Wo2[(size_t)r * 768 + j];
    red[rw][jl] = acc;
    __syncthreads();
    if (rw == 0) {
        float s = bo[j];
#pragma unroll
        for (int i = 0; i < 8; i++) s += red[i][jl];
        g_b3[j] = s;
    }
}

// ----------------------------------------------------------------------------
// Edge bias (softcap) with mask folded
// ----------------------------------------------------------------------------
__global__ void __launch_bounds__(256) eb_kernel(
    const float* __restrict__ edge, const float* __restrict__ We,
    const float* __restrict__ be, const unsigned char* __restrict__ mask)
{
    int idx  = blockIdx.x * 16 + (threadIdx.x >> 4);
    int l16  = threadIdx.x & 15;
    const float4 e4 = *(const float4*)(edge + (size_t)idx * 64 + l16 * 4);
    const float4 w4 = *(const float4*)(We + l16 * 4);
    float acc = e4.x * w4.x + e4.y * w4.y + e4.z * w4.z + e4.w * w4.w;
#pragma unroll
    for (int o = 8; o > 0; o >>= 1)
        acc += __shfl_xor_sync(0xffffffffu, acc, o);
    if (l16 == 0) {
        float x = (acc + be[0]) * INVSQRT2_;
        float r = CAP_ * tanhf(x * (1.0f / CAP_));
        g_eb[idx] = mask[idx] ? -1e9f : r;
    }
}

// ----------------------------------------------------------------------------
// Launch. Streams: s0 = QKV -> attn -> final1 -> final2;
// s1 = eb -> (wait attn) ae_mma; s2 = folds + W3.
// ae_mma is API launch index 3 (ncu capture target).
// ----------------------------------------------------------------------------
extern "C" void kernel_launch(void* const* d_in, const int* in_sizes, int n_in,
                              void* d_out, int out_size)
{
    const float* Q    = (const float*)d_in[0];
    const float* Kin  = (const float*)d_in[1];
    const float* V    = (const float*)d_in[2];
    const unsigned char* mask = (const unsigned char*)d_in[3];
    const float* edge = (const float*)d_in[4];
    const float* Wq   = (const float*)d_in[5];
    const float* bq   = (const float*)d_in[6];
    const float* Wk   = (const float*)d_in[7];
    const float* bk   = (const float*)d_in[8];
    const float* Wv   = (const float*)d_in[9];
    const float* bv   = (const float*)d_in[10];
    const float* Wke  = (const float*)d_in[11];
    const float* bke  = (const float*)d_in[12];
    const float* We   = (const float*)d_in[13];
    const float* be   = (const float*)d_in[14];
    const float* Weo  = (const float*)d_in[15];
    const float* beo  = (const float*)d_in[16];
    const float* Wo   = (const float*)d_in[17];
    const float* bo   = (const float*)d_in[18];
    float* out = (float*)d_out;

    void *pq, *pk, *pv, *pcat, *pW2, *pW3, *pb3;
    cudaGetSymbolAddress(&pq,   g_q);
    cudaGetSymbolAddress(&pk,   g_k);
    cudaGetSymbolAddress(&pv,   g_v);
    cudaGetSymbolAddress(&pcat, g_cat);
    cudaGetSymbolAddress(&pW2,  g_W2);
    cudaGetSymbolAddress(&pW3,  g_W3);
    cudaGetSymbolAddress(&pb3,  g_b3);

    static cudaStream_t s1 = nullptr, s2 = nullptr;
    static cudaEvent_t evA = nullptr, evB = nullptr, evC = nullptr,
                       evD = nullptr, evE = nullptr, evF = nullptr;
    if (!s1) {
        cudaStreamCreateWithFlags(&s1, cudaStreamNonBlocking);
        cudaStreamCreateWithFlags(&s2, cudaStreamNonBlocking);
        cudaEventCreateWithFlags(&evA, cudaEventDisableTiming);
        cudaEventCreateWithFlags(&evB, cudaEventDisableTiming);
        cudaEventCreateWithFlags(&evC, cudaEventDisableTiming);
        cudaEventCreateWithFlags(&evD, cudaEventDisableTiming);
        cudaEventCreateWithFlags(&evE, cudaEventDisableTiming);
        cudaEventCreateWithFlags(&evF, cudaEventDisableTiming);
        cudaFuncSetAttribute(attn_fused, cudaFuncAttributeMaxDynamicSharedMemorySize, ATTN_SMEM);
        cudaFuncSetAttribute(gemm_nn<true>,  cudaFuncAttributeMaxDynamicSharedMemorySize, GNN_SMEM);
        cudaFuncSetAttribute(gemm_nn<false>, cudaFuncAttributeMaxDynamicSharedMemorySize, GNN_SMEM);
    }

    cudaEventRecord(evA, 0);
    cudaStreamWaitEvent(s1, evA, 0);
    cudaStreamWaitEvent(s2, evA, 0);

    // s1: edge bias (needed by attn)
    eb_kernel<<<(B_ * L_ * L_) / 16, 256, 0, s1>>>(edge, We, be, mask);  // 0
    cudaEventRecord(evB, s1);

    // s0: QKV
    {
        GArgs a;
        a.K = 768; a.K1 = 768; a.lda = 768;
        a.g[0] = GArg{Q,   Wq, Wq, bq, (float*)pq};
        a.g[1] = GArg{Kin, Wk, Wk, bk, (float*)pk};
        a.g[2] = GArg{V,   Wv, Wv, bv, (float*)pv};
        gemm_nn<true><<<dim3(6, 16, 3), 256, GNN_SMEM>>>(a);             // 1
    }

    // s0: fused attention (needs eb)
    cudaStreamWaitEvent(0, evB, 0);
    attn_fused<<<dim3(8, B_ * H_), 512, ATTN_SMEM>>>();                  // 2
    cudaEventRecord(evC, 0);

    // s1: ae_mma (needs g_attn) — API launch index 3 (ncu target)
    cudaStreamWaitEvent(s1, evC, 0);
    ae_mma<<<B_ * L_, 128, 0, s1>>>(edge);                               // 3
    cudaEventRecord(evD, s1);

    // s2: weight folds
    build_w2_tile<<<dim3(6, 12), 256, 0, s2>>>(Wke, Weo);                // 4
    build_b2_par<<<24, 256, 0, s2>>>(bke, Weo, beo);                     // 5
    build_b3_par<<<24, 256, 0, s2>>>(Wo + 768 * 768, bo);                // 6
    cudaEventRecord(evF, s2);
    {
        GArgs a;
        a.K = 768; a.K1 = 768; a.lda = 768;
        a.g[0] = GArg{(const float*)pW2, Wo + 768 * 768, Wo, nullptr, (float*)pW3};
        a.g[1] = a.g[0]; a.g[2] = a.g[0];
        gemm_nn<false><<<dim3(6, 6, 1), 256, GNN_SMEM, s2>>>(a);         // 7: W3 = W2@Wo2
    }
    cudaEventRecord(evE, s2);

    // s0: final1 = ctx @ Wo1 + b3 (needs b3; overlaps ae)
    cudaStreamWaitEvent(0, evF, 0);
    {
        GArgs a;
        a.K = 768; a.K1 = 768; a.lda = 1536;
        a.g[0] = GArg{(const float*)pcat, Wo, Wo, (const float*)pb3, out};
        a.g[1] = a.g[0]; a.g[2] = a.g[0];
        gemm_nn64<true, false><<<dim3(6, 32, 1), 128>>>(a);              // 8
    }

    // s0: final2 += ae @ W3 (needs ae + W3)
    cudaStreamWaitEvent(0, evD, 0);
    cudaStreamWaitEvent(0, evE, 0);
    {
        GArgs a;
        a.K = 768; a.K1 = 768; a.lda = 1536;
        a.g[0] = GArg{(const float*)pcat + 768, (const float*)pW3, (const float*)pW3, nullptr, out};
        a.g[1] = a.g[0]; a.g[2] = a.g[0];
        gemm_nn64<false, true><<<dim3(6, 32, 1), 128>>>(a);              // 9
    }
}

// round 13
// speedup vs baseline: 1.1525x; 1.0255x over previous
#include <cuda_runtime.h>
#include <math.h>
#include <stdint.h>

constexpr int B_  = 4;
constexpr int L_  = 512;
constexpr int D_  = 768;
constexpr int H_  = 12;
constexpr int M_  = B_ * L_;
constexpr float SCALE_    = 0.08838834764831845f;
constexpr float INVSQRT2_ = 0.70710678118654752f;
constexpr float CAP_      = 5.0f;

// Scratch
__device__ float g_q   [M_ * D_];
__device__ float g_k   [M_ * D_];
__device__ float g_v   [M_ * D_];
__device__ float g_eb  [B_ * L_ * L_];                // eb with mask folded in
__device__ float g_attn[(size_t)B_ * H_ * L_ * L_];
__device__ float g_cat [M_ * 2 * D_];
__device__ float g_W2  [D_ * D_];
__device__ float g_W3  [D_ * D_];
__device__ float g_b2  [D_];
__device__ float g_b3  [D_];

// ----------------------------------------------------------------------------
// helpers
// ----------------------------------------------------------------------------
__device__ __forceinline__ unsigned f2tf(float x) {
    unsigned u;
    asm("cvt.rna.tf32.f32 %0, %1;" : "=r"(u) : "f"(x));
    return u;
}
__device__ __forceinline__ unsigned cvt_u(unsigned x) {
    return f2tf(__uint_as_float(x));
}
__device__ __forceinline__ void mma8(float* c, const unsigned* a, const unsigned* b) {
    asm volatile(
        "mma.sync.aligned.m16n8k8.row.col.f32.tf32.tf32.f32 "
        "{%0,%1,%2,%3}, {%4,%5,%6,%7}, {%8,%9}, {%0,%1,%2,%3};"
        : "+f"(c[0]), "+f"(c[1]), "+f"(c[2]), "+f"(c[3])
        : "r"(a[0]), "r"(a[1]), "r"(a[2]), "r"(a[3]), "r"(b[0]), "r"(b[1]));
}
__device__ __forceinline__ unsigned smem_u32(const void* p) {
    return (unsigned)__cvta_generic_to_shared(p);
}
__device__ __forceinline__ void ldsm4(unsigned* r, unsigned a) {
    asm volatile("ldmatrix.sync.aligned.m8n8.x4.shared.b16 {%0,%1,%2,%3}, [%4];"
        : "=r"(r[0]), "=r"(r[1]), "=r"(r[2]), "=r"(r[3]) : "r"(a));
}
__device__ __forceinline__ void cp16(unsigned dst, const void* src) {
    asm volatile("cp.async.cg.shared.global [%0], [%1], 16;" :: "r"(dst), "l"(src));
}
__device__ __forceinline__ void cp_commit() {
    asm volatile("cp.async.commit_group;");
}
template<int N>
__device__ __forceinline__ void cp_wait() {
    asm volatile("cp.async.wait_group %0;" :: "n"(N));
}

struct GArg  { const float* A; const float* Bm; const float* B2; const float* bias; float* C; };
struct GArgs { GArg g[3]; int K; int K1; int lda; };

// ----------------------------------------------------------------------------
// NN tf32 GEMM: BM=128 BN=128 BK=16, 256 threads, cp.async 3-stage
// (measured 61us on QKV). Dynamic smem 56832 B. Requires (K/16)%3==0.
// ----------------------------------------------------------------------------
constexpr int GNN_SMEM = (3 * 128 * 20 + 3 * 16 * 136) * 4;   // 56832

template<bool BIAS>
__global__ void __launch_bounds__(256, 2) gemm_nn(GArgs args)
{
    extern __shared__ unsigned dyn[];
    unsigned* Asb[3] = { dyn, dyn + 2560, dyn + 5120 };
    unsigned* Bsb[3] = { dyn + 7680, dyn + 7680 + 2176, dyn + 7680 + 4352 };

    const GArg ga = args.g[blockIdx.z];
    const int K  = args.K;
    const int K1 = args.K1;
    const int T  = K >> 4;

    const int tid  = threadIdx.x;
    const int lane = tid & 31;
    const int wid  = tid >> 5;
    const int grp  = lane >> 2;
    const int tig  = lane & 3;
    const int wm0  = (wid >> 1) * 32;
    const int wn0  = (wid & 1) * 64;
    const int m0   = blockIdx.y * 128;
    const int n0   = blockIdx.x * 128;

    float acc[2][8][4];
#pragma unroll
    for (int i = 0; i < 2; i++)
#pragma unroll
        for (int j = 0; j < 8; j++)
#pragma unroll
            for (int q = 0; q < 4; q++) acc[i][j][q] = 0.f;

    const int a_r = tid >> 1, a_c = (tid & 1) * 8;
    const int b_r = tid >> 4, b_c = (tid & 15) * 8;
    const float* Agbase = ga.A + (size_t)(m0 + a_r) * K + a_c;
    const unsigned a_off = (unsigned)((a_r * 20 + a_c) * 4);
    const unsigned b_off = (unsigned)((b_r * 136 + b_c) * 4);

    const int lrow = wm0 + (lane & 7) + 8 * ((lane >> 3) & 1);
    const int lcol = 4 * (lane >> 4);
    unsigned abf[3];
#pragma unroll
    for (int i = 0; i < 3; i++)
        abf[i] = smem_u32(Asb[i]) + (unsigned)((lrow * 20 + lcol) * 4);
    unsigned asd[3], bsd[3];
#pragma unroll
    for (int i = 0; i < 3; i++) { asd[i] = smem_u32(Asb[i]); bsd[i] = smem_u32(Bsb[i]); }

    auto cp_tile = [&](int it, int buf) {
        const int kk = it * 16;
        const float* as = Agbase + kk;
        cp16(asd[buf] + a_off, as);
        cp16(asd[buf] + a_off + 16, as + 4);
        const int krow = kk + b_r;
        const float* bsrc = (krow < K1 ? ga.Bm + (size_t)krow * 768
                                       : ga.B2 + (size_t)(krow - K1) * 768) + n0 + b_c;
        cp16(bsd[buf] + b_off, bsrc);
        cp16(bsd[buf] + b_off + 16, bsrc + 4);
    };

    auto mma_tile = [&](int buf) {
        const unsigned abase = abf[buf];
        const unsigned* Bp = Bsb[buf];
#pragma unroll
        for (int kc = 0; kc < 16; kc += 8) {
            unsigned af[2][4];
            ldsm4(af[0], abase + (unsigned)(kc * 4));
            ldsm4(af[1], abase + (unsigned)((16 * 20 + kc) * 4));
#pragma unroll
            for (int i = 0; i < 2; i++)
#pragma unroll
                for (int q = 0; q < 4; q++) af[i][q] = cvt_u(af[i][q]);
            unsigned bf[8][2];
#pragma unroll
            for (int j = 0; j < 8; j++) {
                bf[j][0] = cvt_u(Bp[(kc + tig) * 136 + wn0 + j * 8 + grp]);
                bf[j][1] = cvt_u(Bp[(kc + tig + 4) * 136 + wn0 + j * 8 + grp]);
            }
#pragma unroll
            for (int i = 0; i < 2; i++)
#pragma unroll
                for (int j = 0; j < 8; j++) mma8(acc[i][j], af[i], bf[j]);
        }
    };

    cp_tile(0, 0); cp_commit();
    cp_tile(1, 1); cp_commit();

    for (int it = 0; it < T; it += 3) {
        cp_wait<1>(); __syncthreads();
        if (it + 2 < T) cp_tile(it + 2, 2);
        cp_commit();
        mma_tile(0);

        cp_wait<1>(); __syncthreads();
        if (it + 3 < T) cp_tile(it + 3, 0);
        cp_commit();
        mma_tile(1);

        cp_wait<1>(); __syncthreads();
        if (it + 4 < T) cp_tile(it + 4, 1);
        cp_commit();
        mma_tile(2);
    }

#pragma unroll
    for (int i = 0; i < 2; i++) {
        int r0 = m0 + wm0 + i * 16 + grp;
#pragma unroll
        for (int j = 0; j < 8; j++) {
            int c = n0 + wn0 + j * 8 + 2 * tig;
            float b0 = 0.f, b1 = 0.f;
            if (BIAS) { b0 = ga.bias[c]; b1 = ga.bias[c + 1]; }
            *(float2*)&ga.C[(size_t)r0 * 768 + c] =
                make_float2(acc[i][j][0] + b0, acc[i][j][1] + b1);
            *(float2*)&ga.C[(size_t)(r0 + 8) * 768 + c] =
                make_float2(acc[i][j][2] + b0, acc[i][j][3] + b1);
        }
    }
}

// ----------------------------------------------------------------------------
// NN tf32 GEMM: BM=64 BN=128, 128 thr, cp.async 3-stage (unchanged).
// ----------------------------------------------------------------------------
template<bool BIAS, bool ACC>
__global__ void __launch_bounds__(128, 3) gemm_nn64(GArgs args)
{
    const GArg ga = args.g[blockIdx.z];
    const int K   = args.K;
    const int K1  = args.K1;
    const int lda = args.lda;
    const int T   = K >> 4;

    __shared__ alignas(16) unsigned As[3][64 * 20];
    __shared__ alignas(16) unsigned Bs[3][16 * 136];

    const int tid  = threadIdx.x;
    const int lane = tid & 31;
    const int wid  = tid >> 5;
    const int grp  = lane >> 2;
    const int tig  = lane & 3;
    const int wm0  = (wid >> 1) * 32;
    const int wn0  = (wid & 1) * 64;
    const int m0   = blockIdx.y * 64;
    const int n0   = blockIdx.x * 128;

    float acc[2][8][4];
#pragma unroll
    for (int i = 0; i < 2; i++)
#pragma unroll
        for (int j = 0; j < 8; j++)
#pragma unroll
            for (int q = 0; q < 4; q++) acc[i][j][q] = 0.f;

    const int a_r = tid >> 1;
    const int a_c = (tid & 1) * 8;
    const float* Agbase = ga.A + (size_t)(m0 + a_r) * lda + a_c;
    const unsigned a_off = (unsigned)((a_r * 20 + a_c) * 4);
    const int b_r = tid >> 3;
    const int b_c = (tid & 7) * 16;
    const unsigned b_off = (unsigned)((b_r * 136 + b_c) * 4);

    const int lrow = wm0 + (lane & 7) + 8 * ((lane >> 3) & 1);
    const int lcol = 4 * (lane >> 4);
    const unsigned ab0 = smem_u32(As[0]) + (unsigned)((lrow * 20 + lcol) * 4);
    const unsigned ab1 = smem_u32(As[1]) + (unsigned)((lrow * 20 + lcol) * 4);
    const unsigned ab2 = smem_u32(As[2]) + (unsigned)((lrow * 20 + lcol) * 4);

    auto cp_tile = [&](int it, unsigned adst, unsigned bdst) {
        const int kk = it * 16;
        const float* as = Agbase + kk;
#pragma unroll
        for (int c = 0; c < 2; c++) cp16(adst + a_off + c * 16, as + c * 4);
        const int krow = kk + b_r;
        const float* bsrc = (krow < K1 ? ga.Bm + (size_t)krow * 768
                                       : ga.B2 + (size_t)(krow - K1) * 768) + n0 + b_c;
#pragma unroll
        for (int c = 0; c < 4; c++) cp16(bdst + b_off + c * 16, bsrc + c * 4);
    };

    auto mma_tile = [&](unsigned abase, const unsigned* Bsb) {
#pragma unroll
        for (int kc = 0; kc < 16; kc += 8) {
            unsigned af[2][4];
#pragma unroll
            for (int i = 0; i < 2; i++) {
                ldsm4(af[i], abase + (unsigned)((i * 16 * 20 + kc) * 4));
#pragma unroll
                for (int q = 0; q < 4; q++) af[i][q] = cvt_u(af[i][q]);
            }
            unsigned bf[8][2];
#pragma unroll
            for (int j = 0; j < 8; j++) {
                bf[j][0] = cvt_u(Bsb[(kc + tig) * 136 + wn0 + j * 8 + grp]);
                bf[j][1] = cvt_u(Bsb[(kc + tig + 4) * 136 + wn0 + j * 8 + grp]);
            }
#pragma unroll
            for (int i = 0; i < 2; i++)
#pragma unroll
                for (int j = 0; j < 8; j++) mma8(acc[i][j], af[i], bf[j]);
        }
    };

    const unsigned asd0 = smem_u32(As[0]), asd1 = smem_u32(As[1]), asd2 = smem_u32(As[2]);
    const unsigned bsd0 = smem_u32(Bs[0]), bsd1 = smem_u32(Bs[1]), bsd2 = smem_u32(Bs[2]);

    cp_tile(0, asd0, bsd0); cp_commit();
    cp_tile(1, asd1, bsd1); cp_commit();

    for (int it = 0; it < T; it += 3) {
        cp_wait<1>(); __syncthreads();
        if (it + 2 < T) cp_tile(it + 2, asd2, bsd2);
        cp_commit();
        mma_tile(ab0, Bs[0]);

        cp_wait<1>(); __syncthreads();
        if (it + 3 < T) cp_tile(it + 3, asd0, bsd0);
        cp_commit();
        mma_tile(ab1, Bs[1]);

        cp_wait<1>(); __syncthreads();
        if (it + 4 < T) cp_tile(it + 4, asd1, bsd1);
        cp_commit();
        mma_tile(ab2, Bs[2]);
    }

#pragma unroll
    for (int i = 0; i < 2; i++) {
        int r0 = m0 + wm0 + i * 16 + grp;
#pragma unroll
        for (int j = 0; j < 8; j++) {
            int c = n0 + wn0 + j * 8 + 2 * tig;
            float b0 = 0.f, b1 = 0.f;
            if (BIAS) { b0 = ga.bias[c]; b1 = ga.bias[c + 1]; }
            float2 o0 = make_float2(acc[i][j][0] + b0, acc[i][j][1] + b1);
            float2 o1 = make_float2(acc[i][j][2] + b0, acc[i][j][3] + b1);
            float2* p0 = (float2*)&ga.C[(size_t)r0 * 768 + c];
            float2* p1 = (float2*)&ga.C[(size_t)(r0 + 8) * 768 + c];
            if (ACC) {
                float2 e0 = *p0, e1 = *p1;
                o0.x += e0.x; o0.y += e0.y; o1.x += e1.x; o1.y += e1.y;
            }
            *p0 = o0; *p1 = o1;
        }
    }
}

// ----------------------------------------------------------------------------
// Fused attention (64 q-rows, 512 threads, cp.async). bh = bh_base + blockIdx.y
// so it can be launched in batch-halves gated on per-half eb completion.
// ----------------------------------------------------------------------------
constexpr int SC_STRIDE = 516;
constexpr int SC_BYTES  = 64 * SC_STRIDE * 4;
constexpr int QS_BYTES  = 64 * 68 * 4;
constexpr int KV_BYTES  = 128 * 68 * 4;
constexpr int ATTN_SMEM = SC_BYTES + QS_BYTES + 2 * KV_BYTES;  // 219136

__global__ void __launch_bounds__(512, 1) attn_fused(int bh_base)
{
    extern __shared__ char dsm[];
    float*    Sc  = (float*)dsm;
    unsigned* Qs  = (unsigned*)(dsm + SC_BYTES);
    float*    Kv0 = (float*)(dsm + SC_BYTES + QS_BYTES);
    float*    Kv1 = Kv0 + 128 * 68;

    const int bh = bh_base + blockIdx.y;
    const int b  = bh / H_;
    const int h  = bh % H_;
    const int n0 = blockIdx.x * 64;

    const int tid  = threadIdx.x;
    const int lane = tid & 31;
    const int w    = tid >> 5;
    const int grp  = lane >> 2;
    const int tig  = lane & 3;

    {
        int row = tid >> 3, col = (tid & 7) * 8;
        const float* src = g_q + (size_t)(b * 512 + n0 + row) * 768 + h * 64 + col;
        float4 q0 = *(const float4*)src;
        float4 q1 = *(const float4*)(src + 4);
        *(uint4*)&Qs[row * 68 + col]     = make_uint4(f2tf(q0.x), f2tf(q0.y), f2tf(q0.z), f2tf(q0.w));
        *(uint4*)&Qs[row * 68 + col + 4] = make_uint4(f2tf(q1.x), f2tf(q1.y), f2tf(q1.z), f2tf(q1.w));
    }

    const int srow = tid >> 2;
    const int scol = (tid & 3) * 16;
    float* bufs[2] = { Kv0, Kv1 };
    const unsigned bufu[2] = { smem_u32(Kv0), smem_u32(Kv1) };
    auto cp_chunk = [&](const float* basep, int mc, int bi) {
        const float* s = basep + (size_t)(b * 512 + mc + srow) * 768 + h * 64 + scol;
        unsigned dst = bufu[bi] + (unsigned)((srow * 68 + scol) * 4);
        cp16(dst, s); cp16(dst + 16, s + 4); cp16(dst + 32, s + 8); cp16(dst + 48, s + 12);
    };

    cp_chunk(g_k, 0, 0); cp_commit();

    const int qb = (w >> 3) * 32;
    const int mb = (w & 7) * 16;
    const unsigned aq0 = smem_u32(Qs) +
        (unsigned)(((qb + (lane & 7) + 8 * ((lane >> 3) & 1)) * 68 + 4 * (lane >> 4)) * 4);
    const unsigned koff =
        (unsigned)(((mb + (lane & 7) + 8 * (lane >> 4)) * 68 + 4 * ((lane >> 3) & 1)) * 4);

    for (int c = 0; c < 4; c++) {
        cp_wait<0>(); __syncthreads();
        if (c < 3) { cp_chunk(g_k, (c + 1) * 128, (c + 1) & 1); cp_commit(); }

        float acc[2][2][4];
#pragma unroll
        for (int i = 0; i < 2; i++)
#pragma unroll
            for (int j = 0; j < 2; j++)
#pragma unroll
                for (int q = 0; q < 4; q++) acc[i][j][q] = 0.f;

        const unsigned kb = bufu[c & 1] + koff;
#pragma unroll
        for (int kc = 0; kc < 64; kc += 8) {
            unsigned af[2][4];
            ldsm4(af[0], aq0 + (unsigned)(kc * 4));
            ldsm4(af[1], aq0 + (unsigned)((16 * 68 + kc) * 4));
            unsigned t[4];
            ldsm4(t, kb + (unsigned)(kc * 4));
#pragma unroll
            for (int q = 0; q < 4; q++) t[q] = cvt_u(t[q]);
            unsigned bf0[2] = { t[0], t[1] };
            unsigned bf1[2] = { t[2], t[3] };
            mma8(acc[0][0], af[0], bf0); mma8(acc[0][1], af[0], bf1);
            mma8(acc[1][0], af[1], bf0); mma8(acc[1][1], af[1], bf1);
        }

        const int mc = c * 128;
#pragma unroll
        for (int qt = 0; qt < 2; qt++) {
#pragma unroll
            for (int p = 0; p < 2; p++) {
                int row = qb + qt * 16 + grp + p * 8;
#pragma unroll
                for (int mt = 0; mt < 2; mt++) {
                    int col = mc + mb + mt * 8 + 2 * tig;
                    size_t em = (size_t)(b * 512 + n0 + row) * 512 + col;
                    float2 e2 = *(const float2*)&g_eb[em];
                    *(float2*)&Sc[row * SC_STRIDE + col] =
                        make_float2(acc[qt][mt][2 * p]     * SCALE_ + e2.x,
                                    acc[qt][mt][2 * p + 1] * SCALE_ + e2.y);
                }
            }
        }
    }

    cp_chunk(g_v, 0, 0); cp_commit();
    __syncthreads();

#pragma unroll
    for (int r = 0; r < 4; r++) {
        int row = w * 4 + r;
        float4 v[4];
#pragma unroll
        for (int j = 0; j < 4; j++)
            v[j] = *(float4*)&Sc[row * SC_STRIDE + lane * 4 + j * 128];
        float mx = -1e30f;
#pragma unroll
        for (int j = 0; j < 4; j++)
            mx = fmaxf(mx, fmaxf(fmaxf(v[j].x, v[j].y), fmaxf(v[j].z, v[j].w)));
#pragma unroll
        for (int o = 16; o > 0; o >>= 1)
            mx = fmaxf(mx, __shfl_xor_sync(0xffffffffu, mx, o));
        float sum = 0.f;
#pragma unroll
        for (int j = 0; j < 4; j++) {
            v[j].x = __expf(v[j].x - mx); v[j].y = __expf(v[j].y - mx);
            v[j].z = __expf(v[j].z - mx); v[j].w = __expf(v[j].w - mx);
            sum += v[j].x + v[j].y + v[j].z + v[j].w;
        }
#pragma unroll
        for (int o = 16; o > 0; o >>= 1)
            sum += __shfl_xor_sync(0xffffffffu, sum, o);
        float inv = 1.0f / sum;
        float4* gout = (float4*)&g_attn[((size_t)bh * 512 + n0 + row) * 512];
#pragma unroll
        for (int j = 0; j < 4; j++) {
            float4 nv = make_float4(v[j].x * inv, v[j].y * inv, v[j].z * inv, v[j].w * inv);
            gout[lane + j * 32] = nv;
            *(uint4*)&Sc[row * SC_STRIDE + lane * 4 + j * 128] =
                make_uint4(f2tf(nv.x), f2tf(nv.y), f2tf(nv.z), f2tf(nv.w));
        }
    }
    cp_wait<0>(); __syncthreads();

    const int db = (w & 7) * 8;
    float acc2[2][4];
#pragma unroll
    for (int i = 0; i < 2; i++)
#pragma unroll
        for (int q = 0; q < 4; q++) acc2[i][q] = 0.f;

    const unsigned as0 = smem_u32(Sc) +
        (unsigned)(((qb + (lane & 7) + 8 * ((lane >> 3) & 1)) * SC_STRIDE + 4 * (lane >> 4)) * 4);

    for (int c = 0; c < 4; c++) {
        if (c < 3) { cp_chunk(g_v, (c + 1) * 128, (c + 1) & 1); cp_commit(); }
        const float* kvu = bufs[c & 1];
#pragma unroll
        for (int ml = 0; ml < 128; ml += 8) {
            unsigned af[2][4];
            ldsm4(af[0], as0 + (unsigned)((c * 128 + ml) * 4));
            ldsm4(af[1], as0 + (unsigned)((16 * SC_STRIDE + c * 128 + ml) * 4));
            unsigned bf[2];
            bf[0] = f2tf(kvu[(ml + tig) * 68 + db + grp]);
            bf[1] = f2tf(kvu[(ml + tig + 4) * 68 + db + grp]);
            mma8(acc2[0], af[0], bf);
            mma8(acc2[1], af[1], bf);
        }
        if (c < 3) { cp_wait<0>(); __syncthreads(); }
    }

#pragma unroll
    for (int qt = 0; qt < 2; qt++) {
#pragma unroll
        for (int p = 0; p < 2; p++) {
            int row = qb + qt * 16 + grp + p * 8;
            int col = h * 64 + db + 2 * tig;
            *(float2*)&g_cat[(size_t)(b * 512 + n0 + row) * 1536 + col] =
                make_float2(acc2[qt][2 * p], acc2[qt][2 * p + 1]);
        }
    }
}

// ----------------------------------------------------------------------------
// ae via tensor cores, 3-stage cp.async (2 chunks in flight during compute).
// Per (b,n): C(16x64) = attn(16x512 pad) @ edge(512x64). Dyn smem 68352 B.
// ----------------------------------------------------------------------------
constexpr int AE_EG = 64 * 72;                 // floats per edge buffer
constexpr int AE_AM = 16 * 68;                 // floats per attn buffer
constexpr int AE_SMEM = (3 * AE_EG + 3 * AE_AM) * 4;   // 68352

__global__ void __launch_bounds__(128) ae_mma(const float* __restrict__ edge)
{
    extern __shared__ float aesm[];
    float* Egb = aesm;                   // 3 x 64x72
    float* Amb = aesm + 3 * AE_EG;       // 3 x 16x68

    const int bn = blockIdx.x;
    const int b  = bn >> 9;
    const int n  = bn & 511;

    const int tid  = threadIdx.x;
    const int lane = tid & 31;
    const int w    = tid >> 5;
    const int grp  = lane >> 2;
    const int tig  = lane & 3;
    const int wn   = w * 16;

    // zero pad rows 12..15 of all three attn buffers
    for (int i = tid; i < 3 * 4 * 68; i += 128) {
        int bi = i / (4 * 68), r = i % (4 * 68);
        Amb[bi * AE_AM + 12 * 68 + r] = 0.f;
    }

    unsigned egu[3], amu[3];
#pragma unroll
    for (int i = 0; i < 3; i++) {
        egu[i] = smem_u32(Egb + i * AE_EG);
        amu[i] = smem_u32(Amb + i * AE_AM);
    }
    const float* ebase = edge + (size_t)bn * 512 * 64;

    auto cp_edge = [&](int mc, int bi) {
        int row = tid >> 1, ch = (tid & 1) * 32;
        const float* s = ebase + (size_t)(mc + row) * 64 + ch;
        unsigned dst = egu[bi] + (unsigned)((row * 72 + ch) * 4);
#pragma unroll
        for (int c = 0; c < 8; c++) cp16(dst + c * 16, s + c * 4);
    };
    auto cp_attn = [&](int mc, int bi) {
        if (tid < 96) {
            int hh = tid >> 3, seg = (tid & 7) * 8;
            const float* s = g_attn + (((size_t)(b * H_ + hh)) * 512 + n) * 512 + mc + seg;
            unsigned dst = amu[bi] + (unsigned)((hh * 68 + seg) * 4);
            cp16(dst, s); cp16(dst + 16, s + 4);
        }
    };

    cp_attn(0, 0); cp_edge(0, 0); cp_commit();
    cp_attn(64, 1); cp_edge(64, 1); cp_commit();

    const int lrow = (lane & 7) + 8 * ((lane >> 3) & 1);
    const int lcol = 4 * (lane >> 4);

    float acc[2][4];
#pragma unroll
    for (int j = 0; j < 2; j++)
#pragma unroll
        for (int q = 0; q < 4; q++) acc[j][q] = 0.f;

    for (int c = 0; c < 8; c++) {
        if (c < 7) cp_wait<1>(); else cp_wait<0>();
        __syncthreads();
        if (c + 2 < 8) {
            cp_attn((c + 2) * 64, (c + 2) % 3);
            cp_edge((c + 2) * 64, (c + 2) % 3);
            cp_commit();
        }
        const unsigned ab = amu[c % 3] + (unsigned)((lrow * 68 + lcol) * 4);
        const float* E = Egb + (c % 3) * AE_EG;
#pragma unroll
        for (int kc = 0; kc < 64; kc += 8) {
            unsigned af[4];
            ldsm4(af, ab + (unsigned)(kc * 4));
#pragma unroll
            for (int q = 0; q < 4; q++) af[q] = cvt_u(af[q]);
#pragma unroll
            for (int j = 0; j < 2; j++) {
                unsigned bf[2];
                bf[0] = f2tf(E[(kc + tig) * 72 + wn + j * 8 + grp]);
                bf[1] = f2tf(E[(kc + tig + 4) * 72 + wn + j * 8 + grp]);
                mma8(acc[j], af, bf);
            }
        }
    }

    float* ar = g_cat + (size_t)bn * 1536 + 768;
#pragma unroll
    for (int p = 0; p < 2; p++) {
        int row = grp + p * 8;
        if (row < 12) {
#pragma unroll
            for (int j = 0; j < 2; j++) {
                int col = wn + j * 8 + 2 * tig;
                *(float2*)&ar[row * 64 + col] = make_float2(acc[j][2 * p], acc[j][2 * p + 1]);
            }
        }
    }
}

// ----------------------------------------------------------------------------
// Weight folds
// ----------------------------------------------------------------------------
__global__ void __launch_bounds__(256) build_w2_tile(
    const float* __restrict__ Wke, const float* __restrict__ Weo)
{
    __shared__ float Ws[64 * 64];
    const int tid = threadIdx.x;
    const int h   = blockIdx.y;
    const int j0  = blockIdx.x * 128;

#pragma unroll
    for (int i = 0; i < 16; i++)
        Ws[tid + i * 256] = Wke[tid + i * 256];
    __syncthreads();

    const int jl = tid & 127;
    const int c0 = (tid >> 7) * 32;
    float acc[32];
#pragma unroll
    for (int c = 0; c < 32; c++) acc[c] = 0.f;

    for (int e = 0; e < 64; e++) {
        float w = Weo[(size_t)(h * 64 + e) * 768 + j0 + jl];
#pragma unroll
        for (int c = 0; c < 32; c++)
            acc[c] += Ws[(c0 + c) * 64 + e] * w;
    }
#pragma unroll
    for (int c = 0; c < 32; c++)
        g_W2[(size_t)(h * 64 + c0 + c) * 768 + j0 + jl] = acc[c];
}

__global__ void __launch_bounds__(256) build_b2_par(
    const float* __restrict__ bke, const float* __restrict__ Weo,
    const float* __restrict__ beo)
{
    __shared__ float red[8][32];
    const int tid = threadIdx.x;
    const int jl  = tid & 31;
    const int rw  = tid >> 5;
    const int j   = blockIdx.x * 32 + jl;

    float acc = 0.f;
    for (int r = rw; r < 768; r += 8)
        acc += bke[r & 63] * Weo[(size_t)r * 768 + j];
    red[rw][jl] = acc;
    __syncthreads();
    if (rw == 0) {
        float s = beo[j];
#pragma unroll
        for (int i = 0; i < 8; i++) s += red[i][jl];
        g_b2[j] = s;
    }
}

__global__ void __launch_bounds__(256) build_b3_par(
    const float* __restrict__ Wo2, const float* __restrict__ bo)
{
    __shared__ float red[8][32];
    const int tid = threadIdx.x;
    const int jl  = tid & 31;
    const int rw  = tid >> 5;
    const int j   = blockIdx.x * 32 + jl;

    float acc = 0.f;
    for (int r = rw; r < 768; r += 8)
        acc += g_b2[r] * Wo2[(size_t)r * 768 + j];
    red[rw][jl] = acc;
    __syncthreads();
    if (rw == 0) {
        float s = bo[j];
#pragma unroll
        for (int i = 0; i < 8; i++) s += red[i][jl];
        g_b3[j] = s;
    }
}

// ----------------------------------------------------------------------------
// Edge bias (softcap) with mask folded; base selects the batch half.
// ----------------------------------------------------------------------------
__global__ void __launch_bounds__(256) eb_kernel(
    const float* __restrict__ edge, const float* __restrict__ We,
    const float* __restrict__ be, const unsigned char* __restrict__ mask,
    int base)
{
    int idx  = base + blockIdx.x * 16 + (threadIdx.x >> 4);
    int l16  = threadIdx.x & 15;
    const float4 e4 = *(const float4*)(edge + (size_t)idx * 64 + l16 * 4);
    const float4 w4 = *(const float4*)(We + l16 * 4);
    float acc = e4.x * w4.x + e4.y * w4.y + e4.z * w4.z + e4.w * w4.w;
#pragma unroll
    for (int o = 8; o > 0; o >>= 1)
        acc += __shfl_xor_sync(0xffffffffu, acc, o);
    if (l16 == 0) {
        float x = (acc + be[0]) * INVSQRT2_;
        float r = CAP_ * tanhf(x * (1.0f / CAP_));
        g_eb[idx] = mask[idx] ? -1e9f : r;
    }
}

// ----------------------------------------------------------------------------
// Launch. s0: QKV -> attn_h0 -> final1 -> final2; s3: attn_h1;
// s1: eb_h0, eb_h1, ae; s2: folds + W3. attn_h0 is API launch idx 3 (ncu).
// ----------------------------------------------------------------------------
extern "C" void kernel_launch(void* const* d_in, const int* in_sizes, int n_in,
                              void* d_out, int out_size)
{
    const float* Q    = (const float*)d_in[0];
    const float* Kin  = (const float*)d_in[1];
    const float* V    = (const float*)d_in[2];
    const unsigned char* mask = (const unsigned char*)d_in[3];
    const float* edge = (const float*)d_in[4];
    const float* Wq   = (const float*)d_in[5];
    const float* bq   = (const float*)d_in[6];
    const float* Wk   = (const float*)d_in[7];
    const float* bk   = (const float*)d_in[8];
    const float* Wv   = (const float*)d_in[9];
    const float* bv   = (const float*)d_in[10];
    const float* Wke  = (const float*)d_in[11];
    const float* bke  = (const float*)d_in[12];
    const float* We   = (const float*)d_in[13];
    const float* be   = (const float*)d_in[14];
    const float* Weo  = (const float*)d_in[15];
    const float* beo  = (const float*)d_in[16];
    const float* Wo   = (const float*)d_in[17];
    const float* bo   = (const float*)d_in[18];
    float* out = (float*)d_out;

    void *pq, *pk, *pv, *pcat, *pW2, *pW3, *pb3;
    cudaGetSymbolAddress(&pq,   g_q);
    cudaGetSymbolAddress(&pk,   g_k);
    cudaGetSymbolAddress(&pv,   g_v);
    cudaGetSymbolAddress(&pcat, g_cat);
    cudaGetSymbolAddress(&pW2,  g_W2);
    cudaGetSymbolAddress(&pW3,  g_W3);
    cudaGetSymbolAddress(&pb3,  g_b3);

    static cudaStream_t s1 = nullptr, s2 = nullptr, s3 = nullptr;
    static cudaEvent_t evA = nullptr, evB0 = nullptr, evB1 = nullptr, evQ = nullptr,
                       evC0 = nullptr, evC1 = nullptr, evD = nullptr, evE = nullptr,
                       evF = nullptr;
    if (!s1) {
        cudaStreamCreateWithFlags(&s1, cudaStreamNonBlocking);
        cudaStreamCreateWithFlags(&s2, cudaStreamNonBlocking);
        cudaStreamCreateWithFlags(&s3, cudaStreamNonBlocking);
        cudaEventCreateWithFlags(&evA,  cudaEventDisableTiming);
        cudaEventCreateWithFlags(&evB0, cudaEventDisableTiming);
        cudaEventCreateWithFlags(&evB1, cudaEventDisableTiming);
        cudaEventCreateWithFlags(&evQ,  cudaEventDisableTiming);
        cudaEventCreateWithFlags(&evC0, cudaEventDisableTiming);
        cudaEventCreateWithFlags(&evC1, cudaEventDisableTiming);
        cudaEventCreateWithFlags(&evD,  cudaEventDisableTiming);
        cudaEventCreateWithFlags(&evE,  cudaEventDisableTiming);
        cudaEventCreateWithFlags(&evF,  cudaEventDisableTiming);
        cudaFuncSetAttribute(attn_fused, cudaFuncAttributeMaxDynamicSharedMemorySize, ATTN_SMEM);
        cudaFuncSetAttribute(ae_mma,     cudaFuncAttributeMaxDynamicSharedMemorySize, AE_SMEM);
        cudaFuncSetAttribute(gemm_nn<true>,  cudaFuncAttributeMaxDynamicSharedMemorySize, GNN_SMEM);
        cudaFuncSetAttribute(gemm_nn<false>, cudaFuncAttributeMaxDynamicSharedMemorySize, GNN_SMEM);
    }

    const int EB_HALF = B_ * L_ * L_ / 2;     // 524288 elements per half

    cudaEventRecord(evA, 0);
    cudaStreamWaitEvent(s1, evA, 0);
    cudaStreamWaitEvent(s2, evA, 0);
    cudaStreamWaitEvent(s3, evA, 0);

    // s1: edge bias halves (b in {0,1} then {2,3})
    eb_kernel<<<EB_HALF / 16, 256, 0, s1>>>(edge, We, be, mask, 0);          // 0
    cudaEventRecord(evB0, s1);
    eb_kernel<<<EB_HALF / 16, 256, 0, s1>>>(edge, We, be, mask, EB_HALF);    // 1
    cudaEventRecord(evB1, s1);

    // s0: QKV
    {
        GArgs a;
        a.K = 768; a.K1 = 768; a.lda = 768;
        a.g[0] = GArg{Q,   Wq, Wq, bq, (float*)pq};
        a.g[1] = GArg{Kin, Wk, Wk, bk, (float*)pk};
        a.g[2] = GArg{V,   Wv, Wv, bv, (float*)pv};
        gemm_nn<true><<<dim3(6, 16, 3), 256, GNN_SMEM>>>(a);                 // 2
    }
    cudaEventRecord(evQ, 0);

    // s0: attention half 0 (bh 0..23) — API launch index 3 (ncu target)
    cudaStreamWaitEvent(0, evB0, 0);
    attn_fused<<<dim3(8, 24), 512, ATTN_SMEM>>>(0);                          // 3
    cudaEventRecord(evC0, 0);

    // s3: attention half 1 (bh 24..47)
    cudaStreamWaitEvent(s3, evQ, 0);
    cudaStreamWaitEvent(s3, evB1, 0);
    attn_fused<<<dim3(8, 24), 512, ATTN_SMEM, s3>>>(24);                     // 4
    cudaEventRecord(evC1, s3);

    // s1: ae (needs all of g_attn)
    cudaStreamWaitEvent(s1, evC0, 0);
    cudaStreamWaitEvent(s1, evC1, 0);
    ae_mma<<<B_ * L_, 128, AE_SMEM, s1>>>(edge);                             // 5
    cudaEventRecord(evD, s1);

    // s2: weight folds
    build_w2_tile<<<dim3(6, 12), 256, 0, s2>>>(Wke, Weo);                    // 6
    build_b2_par<<<24, 256, 0, s2>>>(bke, Weo, beo);                         // 7
    build_b3_par<<<24, 256, 0, s2>>>(Wo + 768 * 768, bo);                    // 8
    cudaEventRecord(evF, s2);
    {
        GArgs a;
        a.K = 768; a.K1 = 768; a.lda = 768;
        a.g[0] = GArg{(const float*)pW2, Wo + 768 * 768, Wo, nullptr, (float*)pW3};
        a.g[1] = a.g[0]; a.g[2] = a.g[0];
        gemm_nn<false><<<dim3(6, 6, 1), 256, GNN_SMEM, s2>>>(a);             // 9: W3
    }
    cudaEventRecord(evE, s2);

    // s0: final1 = ctx @ Wo1 + b3 (needs both attn halves + b3; overlaps ae)
    cudaStreamWaitEvent(0, evC1, 0);
    cudaStreamWaitEvent(0, evF, 0);
    {
        GArgs a;
        a.K = 768; a.K1 = 768; a.lda = 1536;
        a.g[0] = GArg{(const float*)pcat, Wo, Wo, (const float*)pb3, out};
        a.g[1] = a.g[0]; a.g[2] = a.g[0];
        gemm_nn64<true, false><<<dim3(6, 32, 1), 128>>>(a);                  // 10
    }

    // s0: final2 += ae @ W3 (needs ae + W3)
    cudaStreamWaitEvent(0, evD, 0);
    cudaStreamWaitEvent(0, evE, 0);
    {
        GArgs a;
        a.K = 768; a.K1 = 768; a.lda = 1536;
        a.g[0] = GArg{(const float*)pcat + 768, (const float*)pW3, (const float*)pW3, nullptr, out};
        a.g[1] = a.g[0]; a.g[2] = a.g[0];
        gemm_nn64<false, true><<<dim3(6, 32, 1), 128>>>(a);                  // 11
    }
}